// round 4
// baseline (speedup 1.0000x reference)
#include <cuda_runtime.h>
#include <cuda_bf16.h>
#include <stdint.h>

// ============================================================================
// GPT block via warp-level mma.sync (bf16x3 split precision), sm_100-safe.
// Every GEMM: C = A @ B^T, A[M,K] & B[N,K] row-major bf16 (hi,lo) pairs.
// D = Ahi*Bhi + Ahi*Blo + Alo*Bhi accumulated in fp32 registers.
// ============================================================================

typedef __nv_bfloat16 bf16;

// ---------------- small helpers ----------------
__device__ __forceinline__ uint32_t smem_u32(const void* p) {
    uint32_t a;
    asm("{ .reg .u64 t; cvta.to.shared.u64 t, %1; cvt.u32.u64 %0, t; }"
        : "=r"(a) : "l"(p));
    return a;
}
__device__ __forceinline__ void cp16(uint32_t saddr, const void* g) {
    asm volatile("cp.async.cg.shared.global [%0], [%1], 16;"
                 :: "r"(saddr), "l"(g) : "memory");
}
#define CP_COMMIT() asm volatile("cp.async.commit_group;" ::: "memory")
#define CP_WAIT1()  asm volatile("cp.async.wait_group 1;" ::: "memory")

__device__ __forceinline__ void ldsm4(uint32_t* r, uint32_t a) {
    asm volatile("ldmatrix.sync.aligned.m8n8.x4.shared.b16 {%0,%1,%2,%3}, [%4];"
                 : "=r"(r[0]), "=r"(r[1]), "=r"(r[2]), "=r"(r[3]) : "r"(a));
}
__device__ __forceinline__ void mma16816(float* c, const uint32_t* a,
                                         const uint32_t* b) {
    asm volatile(
        "mma.sync.aligned.m16n8k16.row.col.f32.bf16.bf16.f32 "
        "{%0,%1,%2,%3}, {%4,%5,%6,%7}, {%8,%9}, {%0,%1,%2,%3};"
        : "+f"(c[0]), "+f"(c[1]), "+f"(c[2]), "+f"(c[3])
        : "r"(a[0]), "r"(a[1]), "r"(a[2]), "r"(a[3]), "r"(b[0]), "r"(b[1]));
}

// XOR swizzle: 16B chunk at (row, seg) of a [128 x 32bf16] tile (64B rows).
// Conflict-free for 8-lane ldmatrix phases and cp.async store phases.
__device__ __forceinline__ uint32_t swz(int r, int s) {
    return (uint32_t)(r * 64 + ((s ^ ((r >> 1) & 3)) << 4));
}

__device__ __forceinline__ void split2(float v, bf16& h, bf16& l) {
    h = __float2bfloat16(v);
    l = __float2bfloat16(v - __bfloat162float(h));
}

// ---------------- scratch ----------------
__device__ bf16 g_Xhi[16384LL * 768], g_Xlo[16384LL * 768];
__device__ bf16 g_Wqhi[768 * 768], g_Wqlo[768 * 768];
__device__ bf16 g_Wkhi[768 * 768], g_Wklo[768 * 768];
__device__ bf16 g_Wvhi[768 * 768], g_Wvlo[768 * 768];
__device__ bf16 g_W1hi[3072 * 768], g_W1lo[3072 * 768];
__device__ bf16 g_W2hi[768 * 3072], g_W2lo[768 * 3072];
__device__ bf16 g_Qhi[4LL * 4096 * 768], g_Qlo[4LL * 4096 * 768];
__device__ bf16 g_Khi[4LL * 4096 * 768], g_Klo[4LL * 4096 * 768];
__device__ float g_Vf[4LL * 4096 * 768];
__device__ bf16 g_VThi[4LL * 768 * 4096], g_VTlo[4LL * 768 * 4096];
__device__ float g_S[4LL * 4096 * 4096];
__device__ bf16 g_Phi[4LL * 4096 * 4096], g_Plo[4LL * 4096 * 4096];
__device__ bf16 g_NVhi[4LL * 4096 * 768], g_NVlo[4LL * 4096 * 768];
__device__ bf16 g_Hhi[16384LL * 3072], g_Hlo[16384LL * 3072];

// ---------------- GEMM ----------------
// stage layout: Ahi@0, Alo@8192, Bhi@16384, Blo@24576 ; stage stride 32768
static constexpr int STAGE_BYTES = 32768;
static constexpr int SMEM_TOTAL  = 3 * STAGE_BYTES;

__device__ __forceinline__ void load_stage(
    uint32_t so, int tid,
    const bf16* __restrict__ Ah, const bf16* __restrict__ Al,
    const bf16* __restrict__ Bh, const bf16* __restrict__ Bl,
    long long k0, int K)
{
    const int r = tid & 127, h = tid >> 7;
    const long long ga = (long long)r * K + k0 + h * 16;
#pragma unroll
    for (int u = 0; u < 2; ++u) {
        const uint32_t d = swz(r, h * 2 + u);
        const long long g = ga + u * 8;
        cp16(so + d,         Ah + g);
        cp16(so + 8192 + d,  Al + g);
        cp16(so + 16384 + d, Bh + g);
        cp16(so + 24576 + d, Bl + g);
    }
}

template <bool BIAS, bool RELU, bool PAIR>
__global__ __launch_bounds__(256, 1)
void wm_gemm(const bf16* __restrict__ Ahi, const bf16* __restrict__ Alo,
             const bf16* __restrict__ Bhi, const bf16* __restrict__ Blo,
             const float* __restrict__ bias,
             float* __restrict__ Cf, bf16* __restrict__ Chi, bf16* __restrict__ Clo,
             const int N, const int K,
             const long long bA, const long long bB, const long long bC)
{
    extern __shared__ __align__(128) char smem[];
    const uint32_t sb = smem_u32(smem);
    const int tid = threadIdx.x;
    const int wid = tid >> 5, lane = tid & 31;
    const int wm = wid >> 1, wn = wid & 1;
    const int lj = lane >> 3, lr = lane & 7;

    const long long bm = (long long)blockIdx.y * 128;
    const long long bn = (long long)blockIdx.x * 128;

    const bf16* Ah = Ahi + (long long)blockIdx.z * bA + bm * K;
    const bf16* Al = Alo + (long long)blockIdx.z * bA + bm * K;
    const bf16* Bh = Bhi + (long long)blockIdx.z * bB + bn * K;
    const bf16* Bl = Blo + (long long)blockIdx.z * bB + bn * K;

    float acc[2][8][4];
#pragma unroll
    for (int i = 0; i < 2; ++i)
#pragma unroll
        for (int j = 0; j < 8; ++j)
#pragma unroll
            for (int t = 0; t < 4; ++t) acc[i][j][t] = 0.0f;

    const int NC = K / 32;

    load_stage(sb, tid, Ah, Al, Bh, Bl, 0, K);
    CP_COMMIT();
    load_stage(sb + STAGE_BYTES, tid, Ah, Al, Bh, Bl, 32, K);
    CP_COMMIT();

    int buf = 0;
    for (int c = 0; c < NC; ++c) {
        CP_WAIT1();
        __syncthreads();
        if (c + 2 < NC) {
            int nb = buf + 2; if (nb >= 3) nb -= 3;
            load_stage(sb + nb * STAGE_BYTES, tid, Ah, Al, Bh, Bl,
                       (long long)(c + 2) * 32, K);
        }
        CP_COMMIT();

        const uint32_t bb = sb + buf * STAGE_BYTES;
#pragma unroll
        for (int ks = 0; ks < 2; ++ks) {
            uint32_t Afh[2][4], Afl[2][4];
#pragma unroll
            for (int mt = 0; mt < 2; ++mt) {
                const int row = wm * 32 + mt * 16 + ((lj & 1) << 3) + lr;
                const int seg = ks * 2 + (lj >> 1);
                const uint32_t off = swz(row, seg);
                ldsm4(Afh[mt], bb + off);
                ldsm4(Afl[mt], bb + 8192 + off);
            }
            uint32_t Bfh[4][4], Bfl[4][4];
#pragma unroll
            for (int ntp = 0; ntp < 4; ++ntp) {
                const int row = wn * 64 + ntp * 16 + ((lj >> 1) << 3) + lr;
                const int seg = ks * 2 + (lj & 1);
                const uint32_t off = swz(row, seg);
                ldsm4(Bfh[ntp], bb + 16384 + off);
                ldsm4(Bfl[ntp], bb + 24576 + off);
            }
#pragma unroll
            for (int mt = 0; mt < 2; ++mt)
#pragma unroll
                for (int nt = 0; nt < 8; ++nt) {
                    float* cc = acc[mt][nt];
                    const uint32_t* bhp = &Bfh[nt >> 1][(nt & 1) * 2];
                    const uint32_t* blp = &Bfl[nt >> 1][(nt & 1) * 2];
                    mma16816(cc, Afh[mt], bhp);
                    mma16816(cc, Afh[mt], blp);
                    mma16816(cc, Afl[mt], bhp);
                }
        }
        ++buf; if (buf == 3) buf = 0;
    }

    // ---- epilogue ----
    const long long zC = (long long)blockIdx.z * bC;
    const int rbase = (int)bm + wm * 32 + (lane >> 2);
    const int cbase = (int)bn + wn * 64 + (lane & 3) * 2;

#pragma unroll
    for (int mt = 0; mt < 2; ++mt)
#pragma unroll
        for (int nt = 0; nt < 8; ++nt) {
            const int col = cbase + nt * 8;
            float b0 = 0.f, b1 = 0.f;
            if (BIAS) { b0 = bias[col]; b1 = bias[col + 1]; }
#pragma unroll
            for (int rh = 0; rh < 2; ++rh) {
                const int row = rbase + mt * 16 + rh * 8;
                float v0 = acc[mt][nt][rh * 2 + 0];
                float v1 = acc[mt][nt][rh * 2 + 1];
                if (BIAS) { v0 += b0; v1 += b1; }
                if (RELU) { v0 = fmaxf(v0, 0.f); v1 = fmaxf(v1, 0.f); }
                const long long o = zC + (long long)row * N + col;
                if (PAIR) {
                    bf16 h0, l0, h1, l1;
                    split2(v0, h0, l0);
                    split2(v1, h1, l1);
                    __nv_bfloat162 hp; hp.x = h0; hp.y = h1;
                    __nv_bfloat162 lp; lp.x = l0; lp.y = l1;
                    *(__nv_bfloat162*)(Chi + o) = hp;
                    *(__nv_bfloat162*)(Clo + o) = lp;
                } else {
                    float2 w; w.x = v0; w.y = v1;
                    *(float2*)(Cf + o) = w;
                }
            }
        }
}

// ---------------- fp32 -> (hi,lo) bf16 elementwise ----------------
__global__ __launch_bounds__(256)
void cvt_pair(const float* __restrict__ in, bf16* __restrict__ hi,
              bf16* __restrict__ lo, const long long n)
{
    const long long i = ((long long)blockIdx.x * 256 + threadIdx.x) * 4;
    if (i >= n) return;
    const float4 v = *(const float4*)(in + i);
    __align__(8) bf16 h[4];
    __align__(8) bf16 l[4];
    split2(v.x, h[0], l[0]); split2(v.y, h[1], l[1]);
    split2(v.z, h[2], l[2]); split2(v.w, h[3], l[3]);
    *(uint2*)(hi + i) = *(const uint2*)h;
    *(uint2*)(lo + i) = *(const uint2*)l;
}

// ---------------- V transpose+split: [b,4096,768]f32 -> [b,768,4096] pair ----
__global__ __launch_bounds__(256)
void transpose_cvt(const float* __restrict__ V, bf16* __restrict__ Thi,
                   bf16* __restrict__ Tlo)
{
    __shared__ float tile[32][33];
    const int b = blockIdx.z;
    const int e0 = blockIdx.x * 32;
    const int t0 = blockIdx.y * 32;
    const float* Vb = V + (long long)b * 4096 * 768;
    bf16* Hb = Thi + (long long)b * 768 * 4096;
    bf16* Lb = Tlo + (long long)b * 768 * 4096;
    const int tx = threadIdx.x, ty = threadIdx.y;
#pragma unroll
    for (int j = 0; j < 32; j += 8)
        tile[ty + j][tx] = Vb[(long long)(t0 + ty + j) * 768 + e0 + tx];
    __syncthreads();
#pragma unroll
    for (int j = 0; j < 32; j += 8) {
        bf16 h, l;
        split2(tile[tx][ty + j], h, l);
        const long long o = (long long)(e0 + ty + j) * 4096 + t0 + tx;
        Hb[o] = h;
        Lb[o] = l;
    }
}

// ---------------- softmax (rows of 4096) -> (hi,lo) bf16 ----------------
__global__ __launch_bounds__(256)
void softmax_pair(const float* __restrict__ S, bf16* __restrict__ Phi,
                  bf16* __restrict__ Plo)
{
    __shared__ float red[8];
    const long long row = blockIdx.x;
    const float* p = S + row * 4096;
    const int tid = threadIdx.x, lane = tid & 31, warp = tid >> 5;

    float4 v[4];
#pragma unroll
    for (int i = 0; i < 4; ++i)
        v[i] = *(const float4*)(p + tid * 4 + i * 1024);

    float mx = -3.402823466e38f;
#pragma unroll
    for (int i = 0; i < 4; ++i)
        mx = fmaxf(mx, fmaxf(fmaxf(v[i].x, v[i].y), fmaxf(v[i].z, v[i].w)));
#pragma unroll
    for (int o = 16; o > 0; o >>= 1)
        mx = fmaxf(mx, __shfl_xor_sync(0xffffffffu, mx, o));
    if (lane == 0) red[warp] = mx;
    __syncthreads();
    float rowmax = red[0];
#pragma unroll
    for (int w = 1; w < 8; ++w) rowmax = fmaxf(rowmax, red[w]);
    __syncthreads();

    float sum = 0.0f;
#pragma unroll
    for (int i = 0; i < 4; ++i) {
        v[i].x = __expf(v[i].x - rowmax);
        v[i].y = __expf(v[i].y - rowmax);
        v[i].z = __expf(v[i].z - rowmax);
        v[i].w = __expf(v[i].w - rowmax);
        sum += (v[i].x + v[i].y) + (v[i].z + v[i].w);
    }
#pragma unroll
    for (int o = 16; o > 0; o >>= 1)
        sum += __shfl_xor_sync(0xffffffffu, sum, o);
    if (lane == 0) red[warp] = sum;
    __syncthreads();
    float rowsum = 0.0f;
#pragma unroll
    for (int w = 0; w < 8; ++w) rowsum += red[w];
    const float inv = 1.0f / rowsum;

#pragma unroll
    for (int i = 0; i < 4; ++i) {
        __align__(8) bf16 h[4];
        __align__(8) bf16 l[4];
        split2(v[i].x * inv, h[0], l[0]);
        split2(v[i].y * inv, h[1], l[1]);
        split2(v[i].z * inv, h[2], l[2]);
        split2(v[i].w * inv, h[3], l[3]);
        const long long o = row * 4096 + tid * 4 + i * 1024;
        *(uint2*)(Phi + o) = *(const uint2*)h;
        *(uint2*)(Plo + o) = *(const uint2*)l;
    }
}

// ---------------- host ----------------
extern "C" void kernel_launch(void* const* d_in, const int* in_sizes, int n_in,
                              void* d_out, int out_size)
{
    const float* X  = (const float*)d_in[0];
    const float* Wq = (const float*)d_in[1];
    const float* Wk = (const float*)d_in[2];
    const float* Wv = (const float*)d_in[3];
    const float* W1 = (const float*)d_in[4];
    const float* b1 = (const float*)d_in[5];
    const float* W2 = (const float*)d_in[6];
    const float* b2 = (const float*)d_in[7];
    float* out = (float*)d_out;

    bf16 *Xhi, *Xlo, *Wqhi, *Wqlo, *Wkhi, *Wklo, *Wvhi, *Wvlo;
    bf16 *W1hi, *W1lo, *W2hi, *W2lo;
    bf16 *Qhi, *Qlo, *Khi, *Klo, *VThi, *VTlo, *Phi, *Plo, *NVhi, *NVlo, *Hhi, *Hlo;
    float *Vf, *S;
    cudaGetSymbolAddress((void**)&Xhi, g_Xhi);   cudaGetSymbolAddress((void**)&Xlo, g_Xlo);
    cudaGetSymbolAddress((void**)&Wqhi, g_Wqhi); cudaGetSymbolAddress((void**)&Wqlo, g_Wqlo);
    cudaGetSymbolAddress((void**)&Wkhi, g_Wkhi); cudaGetSymbolAddress((void**)&Wklo, g_Wklo);
    cudaGetSymbolAddress((void**)&Wvhi, g_Wvhi); cudaGetSymbolAddress((void**)&Wvlo, g_Wvlo);
    cudaGetSymbolAddress((void**)&W1hi, g_W1hi); cudaGetSymbolAddress((void**)&W1lo, g_W1lo);
    cudaGetSymbolAddress((void**)&W2hi, g_W2hi); cudaGetSymbolAddress((void**)&W2lo, g_W2lo);
    cudaGetSymbolAddress((void**)&Qhi, g_Qhi);   cudaGetSymbolAddress((void**)&Qlo, g_Qlo);
    cudaGetSymbolAddress((void**)&Khi, g_Khi);   cudaGetSymbolAddress((void**)&Klo, g_Klo);
    cudaGetSymbolAddress((void**)&Vf, g_Vf);
    cudaGetSymbolAddress((void**)&VThi, g_VThi); cudaGetSymbolAddress((void**)&VTlo, g_VTlo);
    cudaGetSymbolAddress((void**)&S, g_S);
    cudaGetSymbolAddress((void**)&Phi, g_Phi);   cudaGetSymbolAddress((void**)&Plo, g_Plo);
    cudaGetSymbolAddress((void**)&NVhi, g_NVhi); cudaGetSymbolAddress((void**)&NVlo, g_NVlo);
    cudaGetSymbolAddress((void**)&Hhi, g_Hhi);   cudaGetSymbolAddress((void**)&Hlo, g_Hlo);

    cudaFuncSetAttribute(wm_gemm<false, false, true>,
                         cudaFuncAttributeMaxDynamicSharedMemorySize, SMEM_TOTAL);
    cudaFuncSetAttribute(wm_gemm<false, false, false>,
                         cudaFuncAttributeMaxDynamicSharedMemorySize, SMEM_TOTAL);
    cudaFuncSetAttribute(wm_gemm<true, true, true>,
                         cudaFuncAttributeMaxDynamicSharedMemorySize, SMEM_TOTAL);
    cudaFuncSetAttribute(wm_gemm<true, false, false>,
                         cudaFuncAttributeMaxDynamicSharedMemorySize, SMEM_TOTAL);

    // split inputs/weights
    cvt_pair<<<12288, 256>>>(X,  Xhi,  Xlo,  16384LL * 768);
    cvt_pair<<<576,  256>>>(Wq, Wqhi, Wqlo, 768LL * 768);
    cvt_pair<<<576,  256>>>(Wk, Wkhi, Wklo, 768LL * 768);
    cvt_pair<<<576,  256>>>(Wv, Wvhi, Wvlo, 768LL * 768);
    cvt_pair<<<2304, 256>>>(W1, W1hi, W1lo, 3072LL * 768);
    cvt_pair<<<2304, 256>>>(W2, W2hi, W2lo, 768LL * 3072);

    // Q = X @ Wq^T, K = X @ Wk^T (pair out); Vf = X @ Wv^T (fp32 out)
    wm_gemm<false, false, true><<<dim3(6, 128, 1), 256, SMEM_TOTAL>>>(
        Xhi, Xlo, Wqhi, Wqlo, nullptr, nullptr, Qhi, Qlo, 768, 768, 0, 0, 0);
    wm_gemm<false, false, true><<<dim3(6, 128, 1), 256, SMEM_TOTAL>>>(
        Xhi, Xlo, Wkhi, Wklo, nullptr, nullptr, Khi, Klo, 768, 768, 0, 0, 0);
    wm_gemm<false, false, false><<<dim3(6, 128, 1), 256, SMEM_TOTAL>>>(
        Xhi, Xlo, Wvhi, Wvlo, nullptr, Vf, nullptr, nullptr, 768, 768, 0, 0, 0);

    // V^T (pair) so attn@V is the same NT GEMM
    transpose_cvt<<<dim3(24, 128, 4), dim3(32, 8)>>>(Vf, VThi, VTlo);

    // scores = Q @ K^T per batch (fp32 out)
    wm_gemm<false, false, false><<<dim3(32, 32, 4), 256, SMEM_TOTAL>>>(
        Qhi, Qlo, Khi, Klo, nullptr, S, nullptr, nullptr, 4096, 768,
        4096LL * 768, 4096LL * 768, 4096LL * 4096);

    // softmax -> P (pair)
    softmax_pair<<<16384, 256>>>(S, Phi, Plo);

    // newV = P @ VT^T per batch (pair out)
    wm_gemm<false, false, true><<<dim3(6, 32, 4), 256, SMEM_TOTAL>>>(
        Phi, Plo, VThi, VTlo, nullptr, nullptr, NVhi, NVlo, 768, 4096,
        4096LL * 4096, 768LL * 4096, 4096LL * 768);

    // H = relu(newV @ W1^T + b1) (pair out)
    wm_gemm<true, true, true><<<dim3(24, 128, 1), 256, SMEM_TOTAL>>>(
        NVhi, NVlo, W1hi, W1lo, b1, nullptr, Hhi, Hlo, 3072, 768, 0, 0, 0);

    // out = H @ W2^T + b2 (fp32 out)
    wm_gemm<true, false, false><<<dim3(6, 128, 1), 256, SMEM_TOTAL>>>(
        Hhi, Hlo, W2hi, W2lo, b2, out, nullptr, nullptr, 768, 3072, 0, 0, 0);
}

// round 5
// speedup vs baseline: 1.0892x; 1.0892x over previous
#include <cuda_runtime.h>
#include <cuda_bf16.h>
#include <stdint.h>

// ============================================================================
// GPT block via warp-level mma.sync (bf16x3 split precision), sm_100-safe.
// Every GEMM: C = A @ B^T, A[M,K] & B[N,K] row-major bf16 (hi,lo) pairs.
// D = Ahi*Bhi + Ahi*Blo + Alo*Bhi accumulated in fp32 registers.
// R5: 2 CTAs/SM (launch_bounds(256,2)), low-reg inner loop.
// ============================================================================

typedef __nv_bfloat16 bf16;

// ---------------- small helpers ----------------
__device__ __forceinline__ uint32_t smem_u32(const void* p) {
    uint32_t a;
    asm("{ .reg .u64 t; cvta.to.shared.u64 t, %1; cvt.u32.u64 %0, t; }"
        : "=r"(a) : "l"(p));
    return a;
}
__device__ __forceinline__ void cp16(uint32_t saddr, const void* g) {
    asm volatile("cp.async.cg.shared.global [%0], [%1], 16;"
                 :: "r"(saddr), "l"(g) : "memory");
}
#define CP_COMMIT() asm volatile("cp.async.commit_group;" ::: "memory")
#define CP_WAIT1()  asm volatile("cp.async.wait_group 1;" ::: "memory")

__device__ __forceinline__ void ldsm4(uint32_t* r, uint32_t a) {
    asm volatile("ldmatrix.sync.aligned.m8n8.x4.shared.b16 {%0,%1,%2,%3}, [%4];"
                 : "=r"(r[0]), "=r"(r[1]), "=r"(r[2]), "=r"(r[3]) : "r"(a));
}
__device__ __forceinline__ void mma16816(float* c, const uint32_t* a,
                                         const uint32_t* b) {
    asm volatile(
        "mma.sync.aligned.m16n8k16.row.col.f32.bf16.bf16.f32 "
        "{%0,%1,%2,%3}, {%4,%5,%6,%7}, {%8,%9}, {%0,%1,%2,%3};"
        : "+f"(c[0]), "+f"(c[1]), "+f"(c[2]), "+f"(c[3])
        : "r"(a[0]), "r"(a[1]), "r"(a[2]), "r"(a[3]), "r"(b[0]), "r"(b[1]));
}

// XOR swizzle: 16B chunk at (row, seg) of a [128 x 32bf16] tile (64B rows).
__device__ __forceinline__ uint32_t swz(int r, int s) {
    return (uint32_t)(r * 64 + ((s ^ ((r >> 1) & 3)) << 4));
}

__device__ __forceinline__ void split2(float v, bf16& h, bf16& l) {
    h = __float2bfloat16(v);
    l = __float2bfloat16(v - __bfloat162float(h));
}

// ---------------- scratch ----------------
__device__ bf16 g_Xhi[16384LL * 768], g_Xlo[16384LL * 768];
__device__ bf16 g_Wqhi[768 * 768], g_Wqlo[768 * 768];
__device__ bf16 g_Wkhi[768 * 768], g_Wklo[768 * 768];
__device__ bf16 g_Wvhi[768 * 768], g_Wvlo[768 * 768];
__device__ bf16 g_W1hi[3072 * 768], g_W1lo[3072 * 768];
__device__ bf16 g_W2hi[768 * 3072], g_W2lo[768 * 3072];
__device__ bf16 g_Qhi[4LL * 4096 * 768], g_Qlo[4LL * 4096 * 768];
__device__ bf16 g_Khi[4LL * 4096 * 768], g_Klo[4LL * 4096 * 768];
__device__ float g_Vf[4LL * 4096 * 768];
__device__ bf16 g_VThi[4LL * 768 * 4096], g_VTlo[4LL * 768 * 4096];
__device__ float g_S[4LL * 4096 * 4096];
__device__ bf16 g_Phi[4LL * 4096 * 4096], g_Plo[4LL * 4096 * 4096];
__device__ bf16 g_NVhi[4LL * 4096 * 768], g_NVlo[4LL * 4096 * 768];
__device__ bf16 g_Hhi[16384LL * 3072], g_Hlo[16384LL * 3072];

// ---------------- GEMM ----------------
// stage layout: Ahi@0, Alo@8192, Bhi@16384, Blo@24576 ; stage stride 32768
static constexpr int STAGE_BYTES = 32768;
static constexpr int SMEM_TOTAL  = 3 * STAGE_BYTES;   // 96KB -> 2 CTAs/SM

__device__ __forceinline__ void load_stage(
    uint32_t so, int tid,
    const bf16* __restrict__ Ah, const bf16* __restrict__ Al,
    const bf16* __restrict__ Bh, const bf16* __restrict__ Bl,
    long long k0, int K)
{
    const int r = tid & 127, h = tid >> 7;
    const long long ga = (long long)r * K + k0 + h * 16;
#pragma unroll
    for (int u = 0; u < 2; ++u) {
        const uint32_t d = swz(r, h * 2 + u);
        const long long g = ga + u * 8;
        cp16(so + d,         Ah + g);
        cp16(so + 8192 + d,  Al + g);
        cp16(so + 16384 + d, Bh + g);
        cp16(so + 24576 + d, Bl + g);
    }
}

template <bool BIAS, bool RELU, bool PAIR>
__global__ __launch_bounds__(256, 2)
void wm_gemm(const bf16* __restrict__ Ahi, const bf16* __restrict__ Alo,
             const bf16* __restrict__ Bhi, const bf16* __restrict__ Blo,
             const float* __restrict__ bias,
             float* __restrict__ Cf, bf16* __restrict__ Chi, bf16* __restrict__ Clo,
             const int N, const int K,
             const long long bA, const long long bB, const long long bC)
{
    extern __shared__ __align__(128) char smem[];
    const uint32_t sb = smem_u32(smem);
    const int tid = threadIdx.x;
    const int wid = tid >> 5, lane = tid & 31;
    const int wm = wid >> 1, wn = wid & 1;
    const int lj = lane >> 3, lr = lane & 7;

    const long long bm = (long long)blockIdx.y * 128;
    const long long bn = (long long)blockIdx.x * 128;

    const bf16* Ah = Ahi + (long long)blockIdx.z * bA + bm * K;
    const bf16* Al = Alo + (long long)blockIdx.z * bA + bm * K;
    const bf16* Bh = Bhi + (long long)blockIdx.z * bB + bn * K;
    const bf16* Bl = Blo + (long long)blockIdx.z * bB + bn * K;

    float acc[2][8][4];
#pragma unroll
    for (int i = 0; i < 2; ++i)
#pragma unroll
        for (int j = 0; j < 8; ++j)
#pragma unroll
            for (int t = 0; t < 4; ++t) acc[i][j][t] = 0.0f;

    const int NC = K / 32;

    load_stage(sb, tid, Ah, Al, Bh, Bl, 0, K);
    CP_COMMIT();
    load_stage(sb + STAGE_BYTES, tid, Ah, Al, Bh, Bl, 32, K);
    CP_COMMIT();

    // precomputed fragment smem offsets (relative to stage base)
    const int arow = wm * 32 + ((lj & 1) << 3) + lr;
    const int aseg = lj >> 1;
    const int brow = wn * 64 + ((lj >> 1) << 3) + lr;
    const int bseg = lj & 1;

    int buf = 0;
    for (int c = 0; c < NC; ++c) {
        CP_WAIT1();
        __syncthreads();
        if (c + 2 < NC) {
            int nb = buf + 2; if (nb >= 3) nb -= 3;
            load_stage(sb + nb * STAGE_BYTES, tid, Ah, Al, Bh, Bl,
                       (long long)(c + 2) * 32, K);
        }
        CP_COMMIT();

        const uint32_t bb = sb + buf * STAGE_BYTES;
#pragma unroll
        for (int ks = 0; ks < 2; ++ks) {
            uint32_t Afh[2][4], Afl[2][4];
#pragma unroll
            for (int mt = 0; mt < 2; ++mt) {
                const uint32_t off = swz(arow + mt * 16, ks * 2 + aseg);
                ldsm4(Afh[mt], bb + off);
                ldsm4(Afl[mt], bb + 8192 + off);
            }
#pragma unroll
            for (int ntp = 0; ntp < 4; ++ntp) {
                uint32_t Bfh[4], Bfl[4];
                const uint32_t off = swz(brow + ntp * 16, ks * 2 + bseg);
                ldsm4(Bfh, bb + 16384 + off);
                ldsm4(Bfl, bb + 24576 + off);
#pragma unroll
                for (int mt = 0; mt < 2; ++mt)
#pragma unroll
                    for (int h = 0; h < 2; ++h) {
                        float* cc = acc[mt][ntp * 2 + h];
                        mma16816(cc, Afh[mt], &Bfh[h * 2]);
                        mma16816(cc, Afl[mt], &Bfh[h * 2]);
                        mma16816(cc, Afh[mt], &Bfl[h * 2]);
                    }
            }
        }
        ++buf; if (buf == 3) buf = 0;
    }

    // ---- epilogue ----
    const long long zC = (long long)blockIdx.z * bC;
    const int rbase = (int)bm + wm * 32 + (lane >> 2);
    const int cbase = (int)bn + wn * 64 + (lane & 3) * 2;

#pragma unroll
    for (int mt = 0; mt < 2; ++mt)
#pragma unroll
        for (int nt = 0; nt < 8; ++nt) {
            const int col = cbase + nt * 8;
            float b0 = 0.f, b1 = 0.f;
            if (BIAS) { b0 = bias[col]; b1 = bias[col + 1]; }
#pragma unroll
            for (int rh = 0; rh < 2; ++rh) {
                const int row = rbase + mt * 16 + rh * 8;
                float v0 = acc[mt][nt][rh * 2 + 0];
                float v1 = acc[mt][nt][rh * 2 + 1];
                if (BIAS) { v0 += b0; v1 += b1; }
                if (RELU) { v0 = fmaxf(v0, 0.f); v1 = fmaxf(v1, 0.f); }
                const long long o = zC + (long long)row * N + col;
                if (PAIR) {
                    bf16 h0, l0, h1, l1;
                    split2(v0, h0, l0);
                    split2(v1, h1, l1);
                    __nv_bfloat162 hp; hp.x = h0; hp.y = h1;
                    __nv_bfloat162 lp; lp.x = l0; lp.y = l1;
                    *(__nv_bfloat162*)(Chi + o) = hp;
                    *(__nv_bfloat162*)(Clo + o) = lp;
                } else {
                    float2 w; w.x = v0; w.y = v1;
                    *(float2*)(Cf + o) = w;
                }
            }
        }
}

// ---------------- fp32 -> (hi,lo) bf16 elementwise ----------------
__global__ __launch_bounds__(256)
void cvt_pair(const float* __restrict__ in, bf16* __restrict__ hi,
              bf16* __restrict__ lo, const long long n)
{
    const long long i = ((long long)blockIdx.x * 256 + threadIdx.x) * 4;
    if (i >= n) return;
    const float4 v = *(const float4*)(in + i);
    __align__(8) bf16 h[4];
    __align__(8) bf16 l[4];
    split2(v.x, h[0], l[0]); split2(v.y, h[1], l[1]);
    split2(v.z, h[2], l[2]); split2(v.w, h[3], l[3]);
    *(uint2*)(hi + i) = *(const uint2*)h;
    *(uint2*)(lo + i) = *(const uint2*)l;
}

// ---------------- V transpose+split: [b,4096,768]f32 -> [b,768,4096] pair ----
__global__ __launch_bounds__(256)
void transpose_cvt(const float* __restrict__ V, bf16* __restrict__ Thi,
                   bf16* __restrict__ Tlo)
{
    __shared__ float tile[32][33];
    const int b = blockIdx.z;
    const int e0 = blockIdx.x * 32;
    const int t0 = blockIdx.y * 32;
    const float* Vb = V + (long long)b * 4096 * 768;
    bf16* Hb = Thi + (long long)b * 768 * 4096;
    bf16* Lb = Tlo + (long long)b * 768 * 4096;
    const int tx = threadIdx.x, ty = threadIdx.y;
#pragma unroll
    for (int j = 0; j < 32; j += 8)
        tile[ty + j][tx] = Vb[(long long)(t0 + ty + j) * 768 + e0 + tx];
    __syncthreads();
#pragma unroll
    for (int j = 0; j < 32; j += 8) {
        bf16 h, l;
        split2(tile[tx][ty + j], h, l);
        const long long o = (long long)(e0 + ty + j) * 4096 + t0 + tx;
        Hb[o] = h;
        Lb[o] = l;
    }
}

// ---------------- softmax (rows of 4096) -> (hi,lo) bf16 ----------------
__global__ __launch_bounds__(256)
void softmax_pair(const float* __restrict__ S, bf16* __restrict__ Phi,
                  bf16* __restrict__ Plo)
{
    __shared__ float red[8];
    const long long row = blockIdx.x;
    const float* p = S + row * 4096;
    const int tid = threadIdx.x, lane = tid & 31, warp = tid >> 5;

    float4 v[4];
#pragma unroll
    for (int i = 0; i < 4; ++i)
        v[i] = *(const float4*)(p + tid * 4 + i * 1024);

    float mx = -3.402823466e38f;
#pragma unroll
    for (int i = 0; i < 4; ++i)
        mx = fmaxf(mx, fmaxf(fmaxf(v[i].x, v[i].y), fmaxf(v[i].z, v[i].w)));
#pragma unroll
    for (int o = 16; o > 0; o >>= 1)
        mx = fmaxf(mx, __shfl_xor_sync(0xffffffffu, mx, o));
    if (lane == 0) red[warp] = mx;
    __syncthreads();
    float rowmax = red[0];
#pragma unroll
    for (int w = 1; w < 8; ++w) rowmax = fmaxf(rowmax, red[w]);
    __syncthreads();

    float sum = 0.0f;
#pragma unroll
    for (int i = 0; i < 4; ++i) {
        v[i].x = __expf(v[i].x - rowmax);
        v[i].y = __expf(v[i].y - rowmax);
        v[i].z = __expf(v[i].z - rowmax);
        v[i].w = __expf(v[i].w - rowmax);
        sum += (v[i].x + v[i].y) + (v[i].z + v[i].w);
    }
#pragma unroll
    for (int o = 16; o > 0; o >>= 1)
        sum += __shfl_xor_sync(0xffffffffu, sum, o);
    if (lane == 0) red[warp] = sum;
    __syncthreads();
    float rowsum = 0.0f;
#pragma unroll
    for (int w = 0; w < 8; ++w) rowsum += red[w];
    const float inv = 1.0f / rowsum;

#pragma unroll
    for (int i = 0; i < 4; ++i) {
        __align__(8) bf16 h[4];
        __align__(8) bf16 l[4];
        split2(v[i].x * inv, h[0], l[0]);
        split2(v[i].y * inv, h[1], l[1]);
        split2(v[i].z * inv, h[2], l[2]);
        split2(v[i].w * inv, h[3], l[3]);
        const long long o = row * 4096 + tid * 4 + i * 1024;
        *(uint2*)(Phi + o) = *(const uint2*)h;
        *(uint2*)(Plo + o) = *(const uint2*)l;
    }
}

// ---------------- host ----------------
extern "C" void kernel_launch(void* const* d_in, const int* in_sizes, int n_in,
                              void* d_out, int out_size)
{
    const float* X  = (const float*)d_in[0];
    const float* Wq = (const float*)d_in[1];
    const float* Wk = (const float*)d_in[2];
    const float* Wv = (const float*)d_in[3];
    const float* W1 = (const float*)d_in[4];
    const float* b1 = (const float*)d_in[5];
    const float* W2 = (const float*)d_in[6];
    const float* b2 = (const float*)d_in[7];
    float* out = (float*)d_out;

    bf16 *Xhi, *Xlo, *Wqhi, *Wqlo, *Wkhi, *Wklo, *Wvhi, *Wvlo;
    bf16 *W1hi, *W1lo, *W2hi, *W2lo;
    bf16 *Qhi, *Qlo, *Khi, *Klo, *VThi, *VTlo, *Phi, *Plo, *NVhi, *NVlo, *Hhi, *Hlo;
    float *Vf, *S;
    cudaGetSymbolAddress((void**)&Xhi, g_Xhi);   cudaGetSymbolAddress((void**)&Xlo, g_Xlo);
    cudaGetSymbolAddress((void**)&Wqhi, g_Wqhi); cudaGetSymbolAddress((void**)&Wqlo, g_Wqlo);
    cudaGetSymbolAddress((void**)&Wkhi, g_Wkhi); cudaGetSymbolAddress((void**)&Wklo, g_Wklo);
    cudaGetSymbolAddress((void**)&Wvhi, g_Wvhi); cudaGetSymbolAddress((void**)&Wvlo, g_Wvlo);
    cudaGetSymbolAddress((void**)&W1hi, g_W1hi); cudaGetSymbolAddress((void**)&W1lo, g_W1lo);
    cudaGetSymbolAddress((void**)&W2hi, g_W2hi); cudaGetSymbolAddress((void**)&W2lo, g_W2lo);
    cudaGetSymbolAddress((void**)&Qhi, g_Qhi);   cudaGetSymbolAddress((void**)&Qlo, g_Qlo);
    cudaGetSymbolAddress((void**)&Khi, g_Khi);   cudaGetSymbolAddress((void**)&Klo, g_Klo);
    cudaGetSymbolAddress((void**)&Vf, g_Vf);
    cudaGetSymbolAddress((void**)&VThi, g_VThi); cudaGetSymbolAddress((void**)&VTlo, g_VTlo);
    cudaGetSymbolAddress((void**)&S, g_S);
    cudaGetSymbolAddress((void**)&Phi, g_Phi);   cudaGetSymbolAddress((void**)&Plo, g_Plo);
    cudaGetSymbolAddress((void**)&NVhi, g_NVhi); cudaGetSymbolAddress((void**)&NVlo, g_NVlo);
    cudaGetSymbolAddress((void**)&Hhi, g_Hhi);   cudaGetSymbolAddress((void**)&Hlo, g_Hlo);

    cudaFuncSetAttribute(wm_gemm<false, false, true>,
                         cudaFuncAttributeMaxDynamicSharedMemorySize, SMEM_TOTAL);
    cudaFuncSetAttribute(wm_gemm<false, false, false>,
                         cudaFuncAttributeMaxDynamicSharedMemorySize, SMEM_TOTAL);
    cudaFuncSetAttribute(wm_gemm<true, true, true>,
                         cudaFuncAttributeMaxDynamicSharedMemorySize, SMEM_TOTAL);
    cudaFuncSetAttribute(wm_gemm<true, false, false>,
                         cudaFuncAttributeMaxDynamicSharedMemorySize, SMEM_TOTAL);

    // split inputs/weights
    cvt_pair<<<12288, 256>>>(X,  Xhi,  Xlo,  16384LL * 768);
    cvt_pair<<<576,  256>>>(Wq, Wqhi, Wqlo, 768LL * 768);
    cvt_pair<<<576,  256>>>(Wk, Wkhi, Wklo, 768LL * 768);
    cvt_pair<<<576,  256>>>(Wv, Wvhi, Wvlo, 768LL * 768);
    cvt_pair<<<2304, 256>>>(W1, W1hi, W1lo, 3072LL * 768);
    cvt_pair<<<2304, 256>>>(W2, W2hi, W2lo, 768LL * 3072);

    // Q = X @ Wq^T, K = X @ Wk^T (pair out); Vf = X @ Wv^T (fp32 out)
    wm_gemm<false, false, true><<<dim3(6, 128, 1), 256, SMEM_TOTAL>>>(
        Xhi, Xlo, Wqhi, Wqlo, nullptr, nullptr, Qhi, Qlo, 768, 768, 0, 0, 0);
    wm_gemm<false, false, true><<<dim3(6, 128, 1), 256, SMEM_TOTAL>>>(
        Xhi, Xlo, Wkhi, Wklo, nullptr, nullptr, Khi, Klo, 768, 768, 0, 0, 0);
    wm_gemm<false, false, false><<<dim3(6, 128, 1), 256, SMEM_TOTAL>>>(
        Xhi, Xlo, Wvhi, Wvlo, nullptr, Vf, nullptr, nullptr, 768, 768, 0, 0, 0);

    // V^T (pair) so attn@V is the same NT GEMM
    transpose_cvt<<<dim3(24, 128, 4), dim3(32, 8)>>>(Vf, VThi, VTlo);

    // scores = Q @ K^T per batch (fp32 out)
    wm_gemm<false, false, false><<<dim3(32, 32, 4), 256, SMEM_TOTAL>>>(
        Qhi, Qlo, Khi, Klo, nullptr, S, nullptr, nullptr, 4096, 768,
        4096LL * 768, 4096LL * 768, 4096LL * 4096);

    // softmax -> P (pair)
    softmax_pair<<<16384, 256>>>(S, Phi, Plo);

    // newV = P @ VT^T per batch (pair out)
    wm_gemm<false, false, true><<<dim3(6, 32, 4), 256, SMEM_TOTAL>>>(
        Phi, Plo, VThi, VTlo, nullptr, nullptr, NVhi, NVlo, 768, 4096,
        4096LL * 4096, 768LL * 4096, 4096LL * 768);

    // H = relu(newV @ W1^T + b1) (pair out)
    wm_gemm<true, true, true><<<dim3(24, 128, 1), 256, SMEM_TOTAL>>>(
        NVhi, NVlo, W1hi, W1lo, b1, nullptr, Hhi, Hlo, 3072, 768, 0, 0, 0);

    // out = H @ W2^T + b2 (fp32 out)
    wm_gemm<true, false, false><<<dim3(6, 128, 1), 256, SMEM_TOTAL>>>(
        Hhi, Hlo, W2hi, W2lo, b2, out, nullptr, nullptr, 768, 3072, 0, 0, 0);
}

// round 6
// speedup vs baseline: 1.4182x; 1.3020x over previous
#include <cuda_runtime.h>
#include <cuda_fp16.h>
#include <stdint.h>

// ============================================================================
// GPT block via warp-level mma.sync, fp16 split precision, sm_100-safe.
// 3-pass GEMMs (logit path): C = Ahi*Bhi + Ahi*Blo + Alo*Bhi  (A,B fp16 pairs)
// 2-pass GEMMs (linear path): C = Ahi*B + Alo*B                (B single fp16)
// fp32 accumulate in registers. All GEMMs: C = A @ B^T, K-major operands.
// ============================================================================

typedef __half h16;

// ---------------- helpers ----------------
__device__ __forceinline__ uint32_t smem_u32(const void* p) {
    uint32_t a;
    asm("{ .reg .u64 t; cvta.to.shared.u64 t, %1; cvt.u32.u64 %0, t; }"
        : "=r"(a) : "l"(p));
    return a;
}
__device__ __forceinline__ void cp16(uint32_t saddr, const void* g) {
    asm volatile("cp.async.cg.shared.global [%0], [%1], 16;"
                 :: "r"(saddr), "l"(g) : "memory");
}
#define CP_COMMIT() asm volatile("cp.async.commit_group;" ::: "memory")
#define CP_WAIT1()  asm volatile("cp.async.wait_group 1;" ::: "memory")

__device__ __forceinline__ void ldsm4(uint32_t* r, uint32_t a) {
    asm volatile("ldmatrix.sync.aligned.m8n8.x4.shared.b16 {%0,%1,%2,%3}, [%4];"
                 : "=r"(r[0]), "=r"(r[1]), "=r"(r[2]), "=r"(r[3]) : "r"(a));
}
__device__ __forceinline__ void mma16816(float* c, const uint32_t* a,
                                         const uint32_t* b) {
    asm volatile(
        "mma.sync.aligned.m16n8k16.row.col.f32.f16.f16.f32 "
        "{%0,%1,%2,%3}, {%4,%5,%6,%7}, {%8,%9}, {%0,%1,%2,%3};"
        : "+f"(c[0]), "+f"(c[1]), "+f"(c[2]), "+f"(c[3])
        : "r"(a[0]), "r"(a[1]), "r"(a[2]), "r"(a[3]), "r"(b[0]), "r"(b[1]));
}

// XOR swizzle: 16B chunk at (row, seg) of a [rows x 32 h16] tile (64B rows).
__device__ __forceinline__ uint32_t swz(int r, int s) {
    return (uint32_t)(r * 64 + ((s ^ ((r >> 1) & 3)) << 4));
}

__device__ __forceinline__ void split2h(float v, h16& h, h16& l) {
    h = __float2half(v);
    l = __float2half(v - __half2float(h));
}

// ---------------- scratch ----------------
__device__ h16 g_Xh[16384LL * 768], g_Xl[16384LL * 768];
__device__ h16 g_Wqh[768 * 768], g_Wql[768 * 768];
__device__ h16 g_Wkh[768 * 768], g_Wkl[768 * 768];
__device__ h16 g_Wvh[768 * 768], g_Wvl[768 * 768];
__device__ h16 g_W1s[3072 * 768];
__device__ h16 g_W2s[768 * 3072];
__device__ h16 g_Qh[4LL * 4096 * 768], g_Ql[4LL * 4096 * 768];
__device__ h16 g_Kh[4LL * 4096 * 768], g_Kl[4LL * 4096 * 768];
__device__ float g_Vf[4LL * 4096 * 768];
__device__ h16 g_VTs[4LL * 768 * 4096];
__device__ float g_S[4LL * 4096 * 4096];
__device__ h16 g_Ph[4LL * 4096 * 4096], g_Pl[4LL * 4096 * 4096];
__device__ h16 g_NVh[4LL * 4096 * 768], g_NVl[4LL * 4096 * 768];
__device__ h16 g_Hh[16384LL * 3072], g_Hl[16384LL * 3072];

// ---------------- GEMM ----------------
// stage layout: Ahi@0, Alo@8192, B(hi)@16384, Blo@24576 (3-pass only)
static constexpr int STAGE_BYTES = 32768;
static constexpr int SMEM_TOTAL  = 3 * STAGE_BYTES;   // 96KB -> 2 CTAs/SM

template <bool THREE>
__device__ __forceinline__ void load_stage(
    uint32_t so, int tid,
    const h16* __restrict__ Ah, const h16* __restrict__ Al,
    const h16* __restrict__ Bh, const h16* __restrict__ Bl,
    long long k0, int K)
{
    const int r = tid & 127, h = tid >> 7;
    const long long ga = (long long)r * K + k0 + h * 16;
#pragma unroll
    for (int u = 0; u < 2; ++u) {
        const uint32_t d = swz(r, h * 2 + u);
        const long long g = ga + u * 8;
        cp16(so + d,         Ah + g);
        cp16(so + 8192 + d,  Al + g);
        cp16(so + 16384 + d, Bh + g);
        if (THREE) cp16(so + 24576 + d, Bl + g);
    }
}

template <bool THREE, bool BIAS, bool RELU, bool PAIR>
__global__ __launch_bounds__(256, 2)
void wm_gemm(const h16* __restrict__ Ahi, const h16* __restrict__ Alo,
             const h16* __restrict__ Bhi, const h16* __restrict__ Blo,
             const float* __restrict__ bias,
             float* __restrict__ Cf, h16* __restrict__ Chi, h16* __restrict__ Clo,
             const int N, const int K,
             const long long bA, const long long bB, const long long bC)
{
    extern __shared__ __align__(128) char smem[];
    const uint32_t sb = smem_u32(smem);
    const int tid = threadIdx.x;
    const int wid = tid >> 5, lane = tid & 31;
    const int wm = wid >> 1, wn = wid & 1;
    const int lj = lane >> 3, lr = lane & 7;

    const long long bm = (long long)blockIdx.y * 128;
    const long long bn = (long long)blockIdx.x * 128;

    const h16* Ah = Ahi + (long long)blockIdx.z * bA + bm * K;
    const h16* Al = Alo + (long long)blockIdx.z * bA + bm * K;
    const h16* Bh = Bhi + (long long)blockIdx.z * bB + bn * K;
    const h16* Bl = THREE ? (Blo + (long long)blockIdx.z * bB + bn * K) : nullptr;

    float acc[2][8][4];
#pragma unroll
    for (int i = 0; i < 2; ++i)
#pragma unroll
        for (int j = 0; j < 8; ++j)
#pragma unroll
            for (int t = 0; t < 4; ++t) acc[i][j][t] = 0.0f;

    const int NC = K / 32;

    load_stage<THREE>(sb, tid, Ah, Al, Bh, Bl, 0, K);
    CP_COMMIT();
    load_stage<THREE>(sb + STAGE_BYTES, tid, Ah, Al, Bh, Bl, 32, K);
    CP_COMMIT();

    const int arow = wm * 32 + ((lj & 1) << 3) + lr;
    const int aseg = lj >> 1;
    const int brow = wn * 64 + ((lj >> 1) << 3) + lr;
    const int bseg = lj & 1;

    int buf = 0;
    for (int c = 0; c < NC; ++c) {
        CP_WAIT1();
        __syncthreads();
        if (c + 2 < NC) {
            int nb = buf + 2; if (nb >= 3) nb -= 3;
            load_stage<THREE>(sb + nb * STAGE_BYTES, tid, Ah, Al, Bh, Bl,
                              (long long)(c + 2) * 32, K);
        }
        CP_COMMIT();

        const uint32_t bb = sb + buf * STAGE_BYTES;
#pragma unroll
        for (int ks = 0; ks < 2; ++ks) {
            uint32_t Afh[2][4], Afl[2][4];
#pragma unroll
            for (int mt = 0; mt < 2; ++mt) {
                const uint32_t off = swz(arow + mt * 16, ks * 2 + aseg);
                ldsm4(Afh[mt], bb + off);
                ldsm4(Afl[mt], bb + 8192 + off);
            }
#pragma unroll
            for (int ntp = 0; ntp < 4; ++ntp) {
                const uint32_t off = swz(brow + ntp * 16, ks * 2 + bseg);
                uint32_t Bfh[4];
                ldsm4(Bfh, bb + 16384 + off);
                if (THREE) {
                    uint32_t Bfl[4];
                    ldsm4(Bfl, bb + 24576 + off);
#pragma unroll
                    for (int mt = 0; mt < 2; ++mt)
#pragma unroll
                        for (int h = 0; h < 2; ++h) {
                            float* cc = acc[mt][ntp * 2 + h];
                            mma16816(cc, Afh[mt], &Bfh[h * 2]);
                            mma16816(cc, Afl[mt], &Bfh[h * 2]);
                            mma16816(cc, Afh[mt], &Bfl[h * 2]);
                        }
                } else {
#pragma unroll
                    for (int mt = 0; mt < 2; ++mt)
#pragma unroll
                        for (int h = 0; h < 2; ++h) {
                            float* cc = acc[mt][ntp * 2 + h];
                            mma16816(cc, Afh[mt], &Bfh[h * 2]);
                            mma16816(cc, Afl[mt], &Bfh[h * 2]);
                        }
                }
            }
        }
        ++buf; if (buf == 3) buf = 0;
    }

    // ---- epilogue ----
    const long long zC = (long long)blockIdx.z * bC;
    const int rbase = (int)bm + wm * 32 + (lane >> 2);
    const int cbase = (int)bn + wn * 64 + (lane & 3) * 2;

#pragma unroll
    for (int mt = 0; mt < 2; ++mt)
#pragma unroll
        for (int nt = 0; nt < 8; ++nt) {
            const int col = cbase + nt * 8;
            float b0 = 0.f, b1 = 0.f;
            if (BIAS) { b0 = bias[col]; b1 = bias[col + 1]; }
#pragma unroll
            for (int rh = 0; rh < 2; ++rh) {
                const int row = rbase + mt * 16 + rh * 8;
                float v0 = acc[mt][nt][rh * 2 + 0];
                float v1 = acc[mt][nt][rh * 2 + 1];
                if (BIAS) { v0 += b0; v1 += b1; }
                if (RELU) { v0 = fmaxf(v0, 0.f); v1 = fmaxf(v1, 0.f); }
                const long long o = zC + (long long)row * N + col;
                if (PAIR) {
                    h16 h0, l0, h1, l1;
                    split2h(v0, h0, l0);
                    split2h(v1, h1, l1);
                    *(__half2*)(Chi + o) = __halves2half2(h0, h1);
                    *(__half2*)(Clo + o) = __halves2half2(l0, l1);
                } else {
                    float2 w; w.x = v0; w.y = v1;
                    *(float2*)(Cf + o) = w;
                }
            }
        }
}

// ---------------- fp32 -> (hi,lo) fp16 elementwise ----------------
__global__ __launch_bounds__(256)
void cvt_pair(const float* __restrict__ in, h16* __restrict__ hi,
              h16* __restrict__ lo, const long long n)
{
    const long long i = ((long long)blockIdx.x * 256 + threadIdx.x) * 4;
    if (i >= n) return;
    const float4 v = *(const float4*)(in + i);
    __align__(8) h16 h[4];
    __align__(8) h16 l[4];
    split2h(v.x, h[0], l[0]); split2h(v.y, h[1], l[1]);
    split2h(v.z, h[2], l[2]); split2h(v.w, h[3], l[3]);
    *(uint2*)(hi + i) = *(const uint2*)h;
    *(uint2*)(lo + i) = *(const uint2*)l;
}

// ---------------- fp32 -> single fp16 elementwise ----------------
__global__ __launch_bounds__(256)
void cvt_single(const float* __restrict__ in, h16* __restrict__ s,
                const long long n)
{
    const long long i = ((long long)blockIdx.x * 256 + threadIdx.x) * 4;
    if (i >= n) return;
    const float4 v = *(const float4*)(in + i);
    __align__(8) h16 h[4];
    h[0] = __float2half(v.x); h[1] = __float2half(v.y);
    h[2] = __float2half(v.z); h[3] = __float2half(v.w);
    *(uint2*)(s + i) = *(const uint2*)h;
}

// ---------------- V transpose: [b,4096,768]f32 -> [b,768,4096] single fp16 ----
__global__ __launch_bounds__(256)
void transpose_cvt(const float* __restrict__ V, h16* __restrict__ Ts)
{
    __shared__ float tile[32][33];
    const int b = blockIdx.z;
    const int e0 = blockIdx.x * 32;
    const int t0 = blockIdx.y * 32;
    const float* Vb = V + (long long)b * 4096 * 768;
    h16* Tb = Ts + (long long)b * 768 * 4096;
    const int tx = threadIdx.x, ty = threadIdx.y;
#pragma unroll
    for (int j = 0; j < 32; j += 8)
        tile[ty + j][tx] = Vb[(long long)(t0 + ty + j) * 768 + e0 + tx];
    __syncthreads();
#pragma unroll
    for (int j = 0; j < 32; j += 8) {
        const long long o = (long long)(e0 + ty + j) * 4096 + t0 + tx;
        Tb[o] = __float2half(tile[tx][ty + j]);
    }
}

// ---------------- softmax (rows of 4096) -> (hi,lo) fp16 ----------------
__global__ __launch_bounds__(256)
void softmax_pair(const float* __restrict__ S, h16* __restrict__ Ph,
                  h16* __restrict__ Pl)
{
    __shared__ float red[8];
    const long long row = blockIdx.x;
    const float* p = S + row * 4096;
    const int tid = threadIdx.x, lane = tid & 31, warp = tid >> 5;

    float4 v[4];
#pragma unroll
    for (int i = 0; i < 4; ++i)
        v[i] = *(const float4*)(p + tid * 4 + i * 1024);

    float mx = -3.402823466e38f;
#pragma unroll
    for (int i = 0; i < 4; ++i)
        mx = fmaxf(mx, fmaxf(fmaxf(v[i].x, v[i].y), fmaxf(v[i].z, v[i].w)));
#pragma unroll
    for (int o = 16; o > 0; o >>= 1)
        mx = fmaxf(mx, __shfl_xor_sync(0xffffffffu, mx, o));
    if (lane == 0) red[warp] = mx;
    __syncthreads();
    float rowmax = red[0];
#pragma unroll
    for (int w = 1; w < 8; ++w) rowmax = fmaxf(rowmax, red[w]);
    __syncthreads();

    float sum = 0.0f;
#pragma unroll
    for (int i = 0; i < 4; ++i) {
        v[i].x = __expf(v[i].x - rowmax);
        v[i].y = __expf(v[i].y - rowmax);
        v[i].z = __expf(v[i].z - rowmax);
        v[i].w = __expf(v[i].w - rowmax);
        sum += (v[i].x + v[i].y) + (v[i].z + v[i].w);
    }
#pragma unroll
    for (int o = 16; o > 0; o >>= 1)
        sum += __shfl_xor_sync(0xffffffffu, sum, o);
    if (lane == 0) red[warp] = sum;
    __syncthreads();
    float rowsum = 0.0f;
#pragma unroll
    for (int w = 0; w < 8; ++w) rowsum += red[w];
    const float inv = 1.0f / rowsum;

#pragma unroll
    for (int i = 0; i < 4; ++i) {
        __align__(8) h16 h[4];
        __align__(8) h16 l[4];
        split2h(v[i].x * inv, h[0], l[0]);
        split2h(v[i].y * inv, h[1], l[1]);
        split2h(v[i].z * inv, h[2], l[2]);
        split2h(v[i].w * inv, h[3], l[3]);
        const long long o = row * 4096 + tid * 4 + i * 1024;
        *(uint2*)(Ph + o) = *(const uint2*)h;
        *(uint2*)(Pl + o) = *(const uint2*)l;
    }
}

// ---------------- host ----------------
extern "C" void kernel_launch(void* const* d_in, const int* in_sizes, int n_in,
                              void* d_out, int out_size)
{
    const float* X  = (const float*)d_in[0];
    const float* Wq = (const float*)d_in[1];
    const float* Wk = (const float*)d_in[2];
    const float* Wv = (const float*)d_in[3];
    const float* W1 = (const float*)d_in[4];
    const float* b1 = (const float*)d_in[5];
    const float* W2 = (const float*)d_in[6];
    const float* b2 = (const float*)d_in[7];
    float* out = (float*)d_out;

    h16 *Xh, *Xl, *Wqh, *Wql, *Wkh, *Wkl, *Wvh, *Wvl, *W1s, *W2s;
    h16 *Qh, *Ql, *Kh, *Kl, *VTs, *Ph, *Pl, *NVh, *NVl, *Hh, *Hl;
    float *Vf, *S;
    cudaGetSymbolAddress((void**)&Xh, g_Xh);    cudaGetSymbolAddress((void**)&Xl, g_Xl);
    cudaGetSymbolAddress((void**)&Wqh, g_Wqh);  cudaGetSymbolAddress((void**)&Wql, g_Wql);
    cudaGetSymbolAddress((void**)&Wkh, g_Wkh);  cudaGetSymbolAddress((void**)&Wkl, g_Wkl);
    cudaGetSymbolAddress((void**)&Wvh, g_Wvh);  cudaGetSymbolAddress((void**)&Wvl, g_Wvl);
    cudaGetSymbolAddress((void**)&W1s, g_W1s);  cudaGetSymbolAddress((void**)&W2s, g_W2s);
    cudaGetSymbolAddress((void**)&Qh, g_Qh);    cudaGetSymbolAddress((void**)&Ql, g_Ql);
    cudaGetSymbolAddress((void**)&Kh, g_Kh);    cudaGetSymbolAddress((void**)&Kl, g_Kl);
    cudaGetSymbolAddress((void**)&Vf, g_Vf);    cudaGetSymbolAddress((void**)&VTs, g_VTs);
    cudaGetSymbolAddress((void**)&S, g_S);
    cudaGetSymbolAddress((void**)&Ph, g_Ph);    cudaGetSymbolAddress((void**)&Pl, g_Pl);
    cudaGetSymbolAddress((void**)&NVh, g_NVh);  cudaGetSymbolAddress((void**)&NVl, g_NVl);
    cudaGetSymbolAddress((void**)&Hh, g_Hh);    cudaGetSymbolAddress((void**)&Hl, g_Hl);

    cudaFuncSetAttribute(wm_gemm<true,  false, false, true>,
                         cudaFuncAttributeMaxDynamicSharedMemorySize, SMEM_TOTAL);
    cudaFuncSetAttribute(wm_gemm<true,  false, false, false>,
                         cudaFuncAttributeMaxDynamicSharedMemorySize, SMEM_TOTAL);
    cudaFuncSetAttribute(wm_gemm<false, false, false, true>,
                         cudaFuncAttributeMaxDynamicSharedMemorySize, SMEM_TOTAL);
    cudaFuncSetAttribute(wm_gemm<false, true,  true,  true>,
                         cudaFuncAttributeMaxDynamicSharedMemorySize, SMEM_TOTAL);
    cudaFuncSetAttribute(wm_gemm<false, true,  false, false>,
                         cudaFuncAttributeMaxDynamicSharedMemorySize, SMEM_TOTAL);

    // launches 0-4 (so launch #5 = Q-proj GEMM lands in the ncu window)
    cvt_pair<<<12288, 256>>>(X,  Xh,  Xl,  16384LL * 768);        // 0
    cvt_pair<<<576,  256>>>(Wq, Wqh, Wql, 768LL * 768);           // 1
    cvt_pair<<<576,  256>>>(Wk, Wkh, Wkl, 768LL * 768);           // 2
    cvt_pair<<<576,  256>>>(Wv, Wvh, Wvl, 768LL * 768);           // 3
    cvt_single<<<2304, 256>>>(W1, W1s, 3072LL * 768);             // 4

    // 5: Q = X @ Wq^T (3-pass, pair out)
    wm_gemm<true, false, false, true><<<dim3(6, 128, 1), 256, SMEM_TOTAL>>>(
        Xh, Xl, Wqh, Wql, nullptr, nullptr, Qh, Ql, 768, 768, 0, 0, 0);
    // 6: K = X @ Wk^T (3-pass, pair out)
    wm_gemm<true, false, false, true><<<dim3(6, 128, 1), 256, SMEM_TOTAL>>>(
        Xh, Xl, Wkh, Wkl, nullptr, nullptr, Kh, Kl, 768, 768, 0, 0, 0);
    // 7: Vf = X @ Wv^T (3-pass, fp32 out)
    wm_gemm<true, false, false, false><<<dim3(6, 128, 1), 256, SMEM_TOTAL>>>(
        Xh, Xl, Wvh, Wvl, nullptr, Vf, nullptr, nullptr, 768, 768, 0, 0, 0);

    cvt_single<<<2304, 256>>>(W2, W2s, 768LL * 3072);             // 8

    // V^T single fp16 so attn@V is the same K-major NT GEMM
    transpose_cvt<<<dim3(24, 128, 4), dim3(32, 8)>>>(Vf, VTs);    // 9

    // scores = Q @ K^T per batch (3-pass, fp32 out)
    wm_gemm<true, false, false, false><<<dim3(32, 32, 4), 256, SMEM_TOTAL>>>(
        Qh, Ql, Kh, Kl, nullptr, S, nullptr, nullptr, 4096, 768,
        4096LL * 768, 4096LL * 768, 4096LL * 4096);

    // softmax -> P (fp16 pair)
    softmax_pair<<<16384, 256>>>(S, Ph, Pl);

    // newV = P @ VT^T per batch (2-pass: P pair x V single, pair out)
    wm_gemm<false, false, false, true><<<dim3(6, 32, 4), 256, SMEM_TOTAL>>>(
        Ph, Pl, VTs, nullptr, nullptr, nullptr, NVh, NVl, 768, 4096,
        4096LL * 4096, 768LL * 4096, 4096LL * 768);

    // H = relu(newV @ W1^T + b1) (2-pass, pair out)
    wm_gemm<false, true, true, true><<<dim3(24, 128, 1), 256, SMEM_TOTAL>>>(
        NVh, NVl, W1s, nullptr, b1, nullptr, Hh, Hl, 3072, 768, 0, 0, 0);

    // out = H @ W2^T + b2 (2-pass, fp32 out)
    wm_gemm<false, true, false, false><<<dim3(6, 128, 1), 256, SMEM_TOTAL>>>(
        Hh, Hl, W2s, nullptr, b2, out, nullptr, nullptr, 768, 3072, 0, 0, 0);
}

// round 9
// speedup vs baseline: 1.4530x; 1.0246x over previous
#include <cuda_runtime.h>
#include <cuda_fp16.h>
#include <stdint.h>

// ============================================================================
// GPT block, sm_100-safe mma.sync. fp16 split precision + int8 corrections.
//   QKV   : fused 3-pass fp16 GEMM (Q,K pair out; V fp32 out)
//   scores: S = q8h*k8l + q8l*k8h (int8 @2x rate, exact s32) + Qh*Kh (fp16)
//   attn@V, FFN1, FFN2 : 2-pass fp16 (A pair x B single)
// R9 fix: s8 A-fragment register order is row-block-fastest (same as fp16),
//         not k-seg-fastest. a1/a2 were swapped in R8.
// ============================================================================

typedef __half h16;

// ---------------- helpers ----------------
__device__ __forceinline__ uint32_t smem_u32(const void* p) {
    uint32_t a;
    asm("{ .reg .u64 t; cvta.to.shared.u64 t, %1; cvt.u32.u64 %0, t; }"
        : "=r"(a) : "l"(p));
    return a;
}
__device__ __forceinline__ void cp16(uint32_t saddr, const void* g) {
    asm volatile("cp.async.cg.shared.global [%0], [%1], 16;"
                 :: "r"(saddr), "l"(g) : "memory");
}
#define CP_COMMIT() asm volatile("cp.async.commit_group;" ::: "memory")
#define CP_WAIT1()  asm volatile("cp.async.wait_group 1;" ::: "memory")

__device__ __forceinline__ void ldsm4(uint32_t* r, uint32_t a) {
    asm volatile("ldmatrix.sync.aligned.m8n8.x4.shared.b16 {%0,%1,%2,%3}, [%4];"
                 : "=r"(r[0]), "=r"(r[1]), "=r"(r[2]), "=r"(r[3]) : "r"(a));
}
__device__ __forceinline__ void mma16816(float* c, const uint32_t* a,
                                         const uint32_t* b) {
    asm volatile(
        "mma.sync.aligned.m16n8k16.row.col.f32.f16.f16.f32 "
        "{%0,%1,%2,%3}, {%4,%5,%6,%7}, {%8,%9}, {%0,%1,%2,%3};"
        : "+f"(c[0]), "+f"(c[1]), "+f"(c[2]), "+f"(c[3])
        : "r"(a[0]), "r"(a[1]), "r"(a[2]), "r"(a[3]), "r"(b[0]), "r"(b[1]));
}
__device__ __forceinline__ void mma_s8(int* c, const uint32_t* a,
                                       const uint32_t* b) {
    asm volatile(
        "mma.sync.aligned.m16n8k32.row.col.s32.s8.s8.s32 "
        "{%0,%1,%2,%3}, {%4,%5,%6,%7}, {%8,%9}, {%0,%1,%2,%3};"
        : "+r"(c[0]), "+r"(c[1]), "+r"(c[2]), "+r"(c[3])
        : "r"(a[0]), "r"(a[1]), "r"(a[2]), "r"(a[3]), "r"(b[0]), "r"(b[1]));
}

// XOR swizzle: 16B chunk at (row, seg) of a 64B-row tile.
__device__ __forceinline__ uint32_t swz(int r, int s) {
    return (uint32_t)(r * 64 + ((s ^ ((r >> 1) & 3)) << 4));
}
__device__ __forceinline__ void split2h(float v, h16& h, h16& l) {
    h = __float2half(v);
    l = __float2half(v - __half2float(h));
}

// ---------------- scratch ----------------
__device__ h16 g_Xh[16384LL * 768], g_Xl[16384LL * 768];
__device__ h16 g_Wch[2304LL * 768], g_Wcl[2304LL * 768];   // fused QKV weights
__device__ h16 g_W1s[3072 * 768];
__device__ h16 g_W2s[768 * 3072];
__device__ h16 g_Qh[4LL * 4096 * 768], g_Ql[4LL * 4096 * 768];
__device__ h16 g_Kh[4LL * 4096 * 768], g_Kl[4LL * 4096 * 768];
__device__ float g_Vf[4LL * 4096 * 768];
__device__ h16 g_VTs[4LL * 768 * 4096];
__device__ float g_S[4LL * 4096 * 4096];
__device__ h16 g_Ph[4LL * 4096 * 4096], g_Pl[4LL * 4096 * 4096];
__device__ h16 g_NVh[4LL * 4096 * 768], g_NVl[4LL * 4096 * 768];
__device__ h16 g_Hh[16384LL * 3072], g_Hl[16384LL * 3072];
__device__ char g_q8h[16384LL * 768], g_q8l[16384LL * 768];
__device__ char g_k8h[16384LL * 768], g_k8l[16384LL * 768];
__device__ float g_sqh[16384], g_sql[16384], g_skh[16384], g_skl[16384];

// ---------------- fp16 GEMM ----------------
// stage: Ah@0, Al@8192, Bh@16384, Bl@24576 ; stride 32768; 3 stages (96KB)
static constexpr int STAGE_BYTES = 32768;
static constexpr int SMEM_TOTAL  = 3 * STAGE_BYTES;

// OM: 0 = f32 store, 1 = pair store, 2 = f32 accumulate, 3 = fused QKV route
template <int PASSES>
__device__ __forceinline__ void load_stage(
    uint32_t so, int tid,
    const h16* __restrict__ Ah, const h16* __restrict__ Al,
    const h16* __restrict__ Bh, const h16* __restrict__ Bl,
    long long k0, int K)
{
    const int r = tid & 127, h = tid >> 7;
#pragma unroll
    for (int u = 0; u < 2; ++u) {
        const uint32_t d = swz(r, h * 2 + u);
        const long long g = (long long)r * K + k0 + (h * 2 + u) * 8;
        cp16(so + d,         Ah + g);
        if (PASSES >= 2) cp16(so + 8192 + d, Al + g);
        cp16(so + 16384 + d, Bh + g);
        if (PASSES == 3)  cp16(so + 24576 + d, Bl + g);
    }
}

template <int PASSES, bool BIAS, bool RELU, int OM>
__global__ __launch_bounds__(256, 2)
void wm_gemm(const h16* __restrict__ Ahi, const h16* __restrict__ Alo,
             const h16* __restrict__ Bhi, const h16* __restrict__ Blo,
             const float* __restrict__ bias,
             float* __restrict__ Cf, h16* __restrict__ Chi, h16* __restrict__ Clo,
             h16* __restrict__ C2hi, h16* __restrict__ C2lo,
             const int N, const int K,
             const long long bA, const long long bB, const long long bC)
{
    extern __shared__ __align__(128) char smem[];
    const uint32_t sb = smem_u32(smem);
    const int tid = threadIdx.x;
    const int wid = tid >> 5, lane = tid & 31;
    const int wm = wid >> 1, wn = wid & 1;
    const int lj = lane >> 3, lr = lane & 7;

    const long long bm = (long long)blockIdx.y * 128;
    const long long bn = (long long)blockIdx.x * 128;

    const h16* Ah = Ahi + (long long)blockIdx.z * bA + bm * K;
    const h16* Al = (PASSES >= 2) ? (Alo + (long long)blockIdx.z * bA + bm * K) : nullptr;
    const h16* Bh = Bhi + (long long)blockIdx.z * bB + bn * K;
    const h16* Bl = (PASSES == 3) ? (Blo + (long long)blockIdx.z * bB + bn * K) : nullptr;

    float acc[2][8][4];
#pragma unroll
    for (int i = 0; i < 2; ++i)
#pragma unroll
        for (int j = 0; j < 8; ++j)
#pragma unroll
            for (int t = 0; t < 4; ++t) acc[i][j][t] = 0.0f;

    const int NC = K / 32;

    load_stage<PASSES>(sb, tid, Ah, Al, Bh, Bl, 0, K);
    CP_COMMIT();
    load_stage<PASSES>(sb + STAGE_BYTES, tid, Ah, Al, Bh, Bl, 32, K);
    CP_COMMIT();

    const int arow = wm * 32 + ((lj & 1) << 3) + lr;
    const int aseg = lj >> 1;
    const int brow = wn * 64 + ((lj >> 1) << 3) + lr;
    const int bseg = lj & 1;

    int buf = 0;
    for (int c = 0; c < NC; ++c) {
        CP_WAIT1();
        __syncthreads();
        if (c + 2 < NC) {
            int nb = buf + 2; if (nb >= 3) nb -= 3;
            load_stage<PASSES>(sb + nb * STAGE_BYTES, tid, Ah, Al, Bh, Bl,
                               (long long)(c + 2) * 32, K);
        }
        CP_COMMIT();

        const uint32_t bb = sb + buf * STAGE_BYTES;
#pragma unroll
        for (int ks = 0; ks < 2; ++ks) {
            uint32_t Afh[2][4], Afl[2][4];
#pragma unroll
            for (int mt = 0; mt < 2; ++mt) {
                const uint32_t off = swz(arow + mt * 16, ks * 2 + aseg);
                ldsm4(Afh[mt], bb + off);
                if (PASSES >= 2) ldsm4(Afl[mt], bb + 8192 + off);
            }
#pragma unroll
            for (int ntp = 0; ntp < 4; ++ntp) {
                const uint32_t off = swz(brow + ntp * 16, ks * 2 + bseg);
                uint32_t Bfh[4];
                ldsm4(Bfh, bb + 16384 + off);
                uint32_t Bfl[4];
                if (PASSES == 3) ldsm4(Bfl, bb + 24576 + off);
#pragma unroll
                for (int mt = 0; mt < 2; ++mt)
#pragma unroll
                    for (int h = 0; h < 2; ++h) {
                        float* cc = acc[mt][ntp * 2 + h];
                        mma16816(cc, Afh[mt], &Bfh[h * 2]);
                        if (PASSES >= 2) mma16816(cc, Afl[mt], &Bfh[h * 2]);
                        if (PASSES == 3) mma16816(cc, Afh[mt], &Bfl[h * 2]);
                    }
            }
        }
        ++buf; if (buf == 3) buf = 0;
    }

    // ---- epilogue ----
    const long long zC = (long long)blockIdx.z * bC;
    const int rbase = (int)bm + wm * 32 + (lane >> 2);
    const int seg   = (OM == 3) ? (int)(bn / 768) : 0;
    const int cbase = (OM == 3)
        ? ((int)bn - seg * 768 + wn * 64 + (lane & 3) * 2)
        : ((int)bn + wn * 64 + (lane & 3) * 2);
    const int cstride = (OM == 3) ? 768 : N;

#pragma unroll
    for (int mt = 0; mt < 2; ++mt)
#pragma unroll
        for (int nt = 0; nt < 8; ++nt) {
            const int col = cbase + nt * 8;
            float b0 = 0.f, b1 = 0.f;
            if (BIAS) { b0 = bias[(int)bn + wn * 64 + (lane & 3) * 2 + nt * 8];
                        b1 = bias[(int)bn + wn * 64 + (lane & 3) * 2 + nt * 8 + 1]; }
#pragma unroll
            for (int rh = 0; rh < 2; ++rh) {
                const int row = rbase + mt * 16 + rh * 8;
                float v0 = acc[mt][nt][rh * 2 + 0];
                float v1 = acc[mt][nt][rh * 2 + 1];
                if (BIAS) { v0 += b0; v1 += b1; }
                if (RELU) { v0 = fmaxf(v0, 0.f); v1 = fmaxf(v1, 0.f); }
                const long long o = zC + (long long)row * cstride + col;
                if (OM == 0) {
                    float2 w; w.x = v0; w.y = v1;
                    *(float2*)(Cf + o) = w;
                } else if (OM == 1) {
                    h16 h0, l0, h1, l1;
                    split2h(v0, h0, l0); split2h(v1, h1, l1);
                    *(__half2*)(Chi + o) = __halves2half2(h0, h1);
                    *(__half2*)(Clo + o) = __halves2half2(l0, l1);
                } else if (OM == 2) {
                    float2 t = *(const float2*)(Cf + o);
                    t.x += v0; t.y += v1;
                    *(float2*)(Cf + o) = t;
                } else {  // OM == 3: fused QKV routing
                    if (seg == 0) {
                        h16 h0, l0, h1, l1;
                        split2h(v0, h0, l0); split2h(v1, h1, l1);
                        *(__half2*)(Chi + o) = __halves2half2(h0, h1);
                        *(__half2*)(Clo + o) = __halves2half2(l0, l1);
                    } else if (seg == 1) {
                        h16 h0, l0, h1, l1;
                        split2h(v0, h0, l0); split2h(v1, h1, l1);
                        *(__half2*)(C2hi + o) = __halves2half2(h0, h1);
                        *(__half2*)(C2lo + o) = __halves2half2(l0, l1);
                    } else {
                        float2 w; w.x = v0; w.y = v1;
                        *(float2*)(Cf + o) = w;
                    }
                }
            }
        }
}

// ---------------- int8 correction GEMM: S (=/+=) (A8@B8^T) * sa_i * sb_j ------
// K=768 fixed, tiles 128x128, BK=64. stage: A@0 (8KB), B@8192; stride 16KB x3.
static constexpr int I8_STAGE = 16384;
static constexpr int I8_SMEM  = 3 * I8_STAGE;

__device__ __forceinline__ void i8_load_stage(uint32_t so, int tid,
    const char* __restrict__ A, const char* __restrict__ B, int k0)
{
    const int r = tid & 127, hf = tid >> 7;
#pragma unroll
    for (int u = 0; u < 2; ++u) {
        const int s = hf * 2 + u;
        const uint32_t d = swz(r, s);
        const long long g = (long long)r * 768 + k0 + s * 16;
        cp16(so + d,        A + g);
        cp16(so + 8192 + d, B + g);
    }
}

template <bool INIT>
__global__ __launch_bounds__(256, 2)
void i8_gemm(const char* __restrict__ A8, const char* __restrict__ B8,
             const float* __restrict__ sa, const float* __restrict__ sb,
             float* __restrict__ S)
{
    extern __shared__ __align__(128) char smem[];
    const uint32_t sbase = smem_u32(smem);
    const int tid = threadIdx.x;
    const int wid = tid >> 5, lane = tid & 31;
    const int wm = wid >> 1, wn = wid & 1;
    const int lj = lane >> 3, lr = lane & 7;
    const int z = blockIdx.z;
    const long long bm = (long long)blockIdx.y * 128;
    const long long bn = (long long)blockIdx.x * 128;

    const char* Ab = A8 + (long long)z * 4096 * 768 + bm * 768;
    const char* Bb = B8 + (long long)z * 4096 * 768 + bn * 768;
    const float* sav = sa + z * 4096 + bm;
    const float* sbv = sb + z * 4096 + bn;

    int acc[2][8][4];
#pragma unroll
    for (int i = 0; i < 2; ++i)
#pragma unroll
        for (int j = 0; j < 8; ++j)
#pragma unroll
            for (int t = 0; t < 4; ++t) acc[i][j][t] = 0;

    i8_load_stage(sbase, tid, Ab, Bb, 0);
    CP_COMMIT();
    i8_load_stage(sbase + I8_STAGE, tid, Ab, Bb, 64);
    CP_COMMIT();

    // s8 fragment order == fp16 order: row-block fastest for A (a0,a1 = row
    // g,g+8 k-first; a2,a3 = k-second); k-seg fastest for B pairs.
    const int arow = wm * 32 + ((lj & 1) << 3) + lr;
    const int aso  = lj >> 1;
    const int brow = wn * 64 + ((lj >> 1) << 3) + lr;
    const int bso  = lj & 1;

    int buf = 0;
    for (int c = 0; c < 12; ++c) {
        CP_WAIT1();
        __syncthreads();
        if (c + 2 < 12) {
            int nb = buf + 2; if (nb >= 3) nb -= 3;
            i8_load_stage(sbase + nb * I8_STAGE, tid, Ab, Bb, (c + 2) * 64);
        }
        CP_COMMIT();

        const uint32_t bb = sbase + buf * I8_STAGE;
#pragma unroll
        for (int step = 0; step < 2; ++step) {
            uint32_t Af[2][4];
#pragma unroll
            for (int mt = 0; mt < 2; ++mt)
                ldsm4(Af[mt], bb + swz(arow + mt * 16, step * 2 + aso));
#pragma unroll
            for (int ntp = 0; ntp < 4; ++ntp) {
                uint32_t Bf[4];
                ldsm4(Bf, bb + 8192 + swz(brow + ntp * 16, step * 2 + bso));
#pragma unroll
                for (int mt = 0; mt < 2; ++mt)
#pragma unroll
                    for (int h = 0; h < 2; ++h)
                        mma_s8(acc[mt][ntp * 2 + h], Af[mt], &Bf[h * 2]);
            }
        }
        ++buf; if (buf == 3) buf = 0;
    }

    // epilogue: scale + write/accumulate into S
    const int rb = wm * 32 + (lane >> 2);
    const int cb = wn * 64 + (lane & 3) * 2;
    const long long zS = (long long)z * 4096 * 4096;
#pragma unroll
    for (int mt = 0; mt < 2; ++mt)
#pragma unroll
        for (int rh = 0; rh < 2; ++rh) {
            const int lrw = rb + mt * 16 + rh * 8;
            const float sA = sav[lrw];
#pragma unroll
            for (int nt = 0; nt < 8; ++nt) {
                const int lc = cb + nt * 8;
                const float c0 = (float)acc[mt][nt][rh * 2 + 0] * sA * sbv[lc];
                const float c1 = (float)acc[mt][nt][rh * 2 + 1] * sA * sbv[lc + 1];
                const long long o = zS + (bm + lrw) * 4096 + bn + lc;
                if (INIT) {
                    float2 w; w.x = c0; w.y = c1;
                    *(float2*)(S + o) = w;
                } else {
                    float2 t = *(const float2*)(S + o);
                    t.x += c0; t.y += c1;
                    *(float2*)(S + o) = t;
                }
            }
        }
}

// ---------------- per-row int8 quantization of (hi,lo) fp16 pair ----------------
__global__ __launch_bounds__(256)
void quant_rows(const h16* __restrict__ Ah, const h16* __restrict__ Al,
                char* __restrict__ q8h, char* __restrict__ q8l,
                float* __restrict__ sh, float* __restrict__ sl)
{
    __shared__ float red[8][2];
    const long long row = blockIdx.x;
    const int tid = threadIdx.x, lane = tid & 31, warp = tid >> 5;
    const h16* ph = Ah + row * 768;
    const h16* pl = Al + row * 768;

    float vh[3], vl[3];
    float mh = 0.f, ml = 0.f;
#pragma unroll
    for (int i = 0; i < 3; ++i) {
        vh[i] = __half2float(ph[tid + i * 256]);
        vl[i] = __half2float(pl[tid + i * 256]);
        mh = fmaxf(mh, fabsf(vh[i]));
        ml = fmaxf(ml, fabsf(vl[i]));
    }
#pragma unroll
    for (int o = 16; o > 0; o >>= 1) {
        mh = fmaxf(mh, __shfl_xor_sync(0xffffffffu, mh, o));
        ml = fmaxf(ml, __shfl_xor_sync(0xffffffffu, ml, o));
    }
    if (lane == 0) { red[warp][0] = mh; red[warp][1] = ml; }
    __syncthreads();
    mh = red[0][0]; ml = red[0][1];
#pragma unroll
    for (int w = 1; w < 8; ++w) {
        mh = fmaxf(mh, red[w][0]);
        ml = fmaxf(ml, red[w][1]);
    }
    mh = fmaxf(mh, 1e-20f);
    ml = fmaxf(ml, 1e-20f);
    const float ih = 127.f / mh, il = 127.f / ml;
#pragma unroll
    for (int i = 0; i < 3; ++i) {
        q8h[row * 768 + tid + i * 256] = (char)__float2int_rn(vh[i] * ih);
        q8l[row * 768 + tid + i * 256] = (char)__float2int_rn(vl[i] * il);
    }
    if (tid == 0) { sh[row] = mh / 127.f; sl[row] = ml / 127.f; }
}

// ---------------- fp32 -> (hi,lo) fp16 ----------------
__global__ __launch_bounds__(256)
void cvt_pair(const float* __restrict__ in, h16* __restrict__ hi,
              h16* __restrict__ lo, const long long n)
{
    const long long i = ((long long)blockIdx.x * 256 + threadIdx.x) * 4;
    if (i >= n) return;
    const float4 v = *(const float4*)(in + i);
    __align__(8) h16 h[4];
    __align__(8) h16 l[4];
    split2h(v.x, h[0], l[0]); split2h(v.y, h[1], l[1]);
    split2h(v.z, h[2], l[2]); split2h(v.w, h[3], l[3]);
    *(uint2*)(hi + i) = *(const uint2*)h;
    *(uint2*)(lo + i) = *(const uint2*)l;
}

// ---------------- fp32 -> single fp16 ----------------
__global__ __launch_bounds__(256)
void cvt_single(const float* __restrict__ in, h16* __restrict__ s,
                const long long n)
{
    const long long i = ((long long)blockIdx.x * 256 + threadIdx.x) * 4;
    if (i >= n) return;
    const float4 v = *(const float4*)(in + i);
    __align__(8) h16 h[4];
    h[0] = __float2half(v.x); h[1] = __float2half(v.y);
    h[2] = __float2half(v.z); h[3] = __float2half(v.w);
    *(uint2*)(s + i) = *(const uint2*)h;
}

// ---------------- V transpose: [b,4096,768]f32 -> [b,768,4096] fp16 ----------
__global__ __launch_bounds__(256)
void transpose_cvt(const float* __restrict__ V, h16* __restrict__ Ts)
{
    __shared__ float tile[32][33];
    const int b = blockIdx.z;
    const int e0 = blockIdx.x * 32;
    const int t0 = blockIdx.y * 32;
    const float* Vb = V + (long long)b * 4096 * 768;
    h16* Tb = Ts + (long long)b * 768 * 4096;
    const int tx = threadIdx.x, ty = threadIdx.y;
#pragma unroll
    for (int j = 0; j < 32; j += 8)
        tile[ty + j][tx] = Vb[(long long)(t0 + ty + j) * 768 + e0 + tx];
    __syncthreads();
#pragma unroll
    for (int j = 0; j < 32; j += 8) {
        const long long o = (long long)(e0 + ty + j) * 4096 + t0 + tx;
        Tb[o] = __float2half(tile[tx][ty + j]);
    }
}

// ---------------- softmax (rows of 4096) -> (hi,lo) fp16 ----------------
__global__ __launch_bounds__(256)
void softmax_pair(const float* __restrict__ S, h16* __restrict__ Ph,
                  h16* __restrict__ Pl)
{
    __shared__ float red[8];
    const long long row = blockIdx.x;
    const float* p = S + row * 4096;
    const int tid = threadIdx.x, lane = tid & 31, warp = tid >> 5;

    float4 v[4];
#pragma unroll
    for (int i = 0; i < 4; ++i)
        v[i] = *(const float4*)(p + tid * 4 + i * 1024);

    float mx = -3.402823466e38f;
#pragma unroll
    for (int i = 0; i < 4; ++i)
        mx = fmaxf(mx, fmaxf(fmaxf(v[i].x, v[i].y), fmaxf(v[i].z, v[i].w)));
#pragma unroll
    for (int o = 16; o > 0; o >>= 1)
        mx = fmaxf(mx, __shfl_xor_sync(0xffffffffu, mx, o));
    if (lane == 0) red[warp] = mx;
    __syncthreads();
    float rowmax = red[0];
#pragma unroll
    for (int w = 1; w < 8; ++w) rowmax = fmaxf(rowmax, red[w]);
    __syncthreads();

    float sum = 0.0f;
#pragma unroll
    for (int i = 0; i < 4; ++i) {
        v[i].x = __expf(v[i].x - rowmax);
        v[i].y = __expf(v[i].y - rowmax);
        v[i].z = __expf(v[i].z - rowmax);
        v[i].w = __expf(v[i].w - rowmax);
        sum += (v[i].x + v[i].y) + (v[i].z + v[i].w);
    }
#pragma unroll
    for (int o = 16; o > 0; o >>= 1)
        sum += __shfl_xor_sync(0xffffffffu, sum, o);
    if (lane == 0) red[warp] = sum;
    __syncthreads();
    float rowsum = 0.0f;
#pragma unroll
    for (int w = 0; w < 8; ++w) rowsum += red[w];
    const float inv = 1.0f / rowsum;

#pragma unroll
    for (int i = 0; i < 4; ++i) {
        __align__(8) h16 h[4];
        __align__(8) h16 l[4];
        split2h(v[i].x * inv, h[0], l[0]);
        split2h(v[i].y * inv, h[1], l[1]);
        split2h(v[i].z * inv, h[2], l[2]);
        split2h(v[i].w * inv, h[3], l[3]);
        const long long o = row * 4096 + tid * 4 + i * 1024;
        *(uint2*)(Ph + o) = *(const uint2*)h;
        *(uint2*)(Pl + o) = *(const uint2*)l;
    }
}

// ---------------- host ----------------
extern "C" void kernel_launch(void* const* d_in, const int* in_sizes, int n_in,
                              void* d_out, int out_size)
{
    const float* X  = (const float*)d_in[0];
    const float* Wq = (const float*)d_in[1];
    const float* Wk = (const float*)d_in[2];
    const float* Wv = (const float*)d_in[3];
    const float* W1 = (const float*)d_in[4];
    const float* b1 = (const float*)d_in[5];
    const float* W2 = (const float*)d_in[6];
    const float* b2 = (const float*)d_in[7];
    float* out = (float*)d_out;

    h16 *Xh, *Xl, *Wch, *Wcl, *W1s, *W2s;
    h16 *Qh, *Ql, *Kh, *Kl, *VTs, *Ph, *Pl, *NVh, *NVl, *Hh, *Hl;
    float *Vf, *S, *sqh, *sql, *skh, *skl;
    char *q8h, *q8l, *k8h, *k8l;
    cudaGetSymbolAddress((void**)&Xh, g_Xh);    cudaGetSymbolAddress((void**)&Xl, g_Xl);
    cudaGetSymbolAddress((void**)&Wch, g_Wch);  cudaGetSymbolAddress((void**)&Wcl, g_Wcl);
    cudaGetSymbolAddress((void**)&W1s, g_W1s);  cudaGetSymbolAddress((void**)&W2s, g_W2s);
    cudaGetSymbolAddress((void**)&Qh, g_Qh);    cudaGetSymbolAddress((void**)&Ql, g_Ql);
    cudaGetSymbolAddress((void**)&Kh, g_Kh);    cudaGetSymbolAddress((void**)&Kl, g_Kl);
    cudaGetSymbolAddress((void**)&Vf, g_Vf);    cudaGetSymbolAddress((void**)&VTs, g_VTs);
    cudaGetSymbolAddress((void**)&S, g_S);
    cudaGetSymbolAddress((void**)&Ph, g_Ph);    cudaGetSymbolAddress((void**)&Pl, g_Pl);
    cudaGetSymbolAddress((void**)&NVh, g_NVh);  cudaGetSymbolAddress((void**)&NVl, g_NVl);
    cudaGetSymbolAddress((void**)&Hh, g_Hh);    cudaGetSymbolAddress((void**)&Hl, g_Hl);
    cudaGetSymbolAddress((void**)&q8h, g_q8h);  cudaGetSymbolAddress((void**)&q8l, g_q8l);
    cudaGetSymbolAddress((void**)&k8h, g_k8h);  cudaGetSymbolAddress((void**)&k8l, g_k8l);
    cudaGetSymbolAddress((void**)&sqh, g_sqh);  cudaGetSymbolAddress((void**)&sql, g_sql);
    cudaGetSymbolAddress((void**)&skh, g_skh);  cudaGetSymbolAddress((void**)&skl, g_skl);

    cudaFuncSetAttribute(wm_gemm<3, false, false, 3>,
                         cudaFuncAttributeMaxDynamicSharedMemorySize, SMEM_TOTAL);
    cudaFuncSetAttribute(wm_gemm<1, false, false, 2>,
                         cudaFuncAttributeMaxDynamicSharedMemorySize, SMEM_TOTAL);
    cudaFuncSetAttribute(wm_gemm<2, false, false, 1>,
                         cudaFuncAttributeMaxDynamicSharedMemorySize, SMEM_TOTAL);
    cudaFuncSetAttribute(wm_gemm<2, true, true, 1>,
                         cudaFuncAttributeMaxDynamicSharedMemorySize, SMEM_TOTAL);
    cudaFuncSetAttribute(wm_gemm<2, true, false, 0>,
                         cudaFuncAttributeMaxDynamicSharedMemorySize, SMEM_TOTAL);
    cudaFuncSetAttribute(i8_gemm<true>,
                         cudaFuncAttributeMaxDynamicSharedMemorySize, I8_SMEM);
    cudaFuncSetAttribute(i8_gemm<false>,
                         cudaFuncAttributeMaxDynamicSharedMemorySize, I8_SMEM);

    // splits
    cvt_pair<<<12288, 256>>>(X,  Xh,  Xl,  16384LL * 768);
    cvt_pair<<<576,  256>>>(Wq, Wch,              Wcl,              768LL * 768);
    cvt_pair<<<576,  256>>>(Wk, Wch + 768 * 768,  Wcl + 768 * 768,  768LL * 768);
    cvt_pair<<<576,  256>>>(Wv, Wch + 1536 * 768, Wcl + 1536 * 768, 768LL * 768);
    cvt_single<<<2304, 256>>>(W1, W1s, 3072LL * 768);

    // fused QKV: [16384,2304] = X @ Wcat^T ; Q,K pair out; V fp32 out
    wm_gemm<3, false, false, 3><<<dim3(18, 128, 1), 256, SMEM_TOTAL>>>(
        Xh, Xl, Wch, Wcl, nullptr, Vf, Qh, Ql, Kh, Kl, 2304, 768, 0, 0, 0);

    quant_rows<<<16384, 256>>>(Qh, Ql, q8h, q8l, sqh, sql);
    quant_rows<<<16384, 256>>>(Kh, Kl, k8h, k8l, skh, skl);
    cvt_single<<<2304, 256>>>(W2, W2s, 768LL * 3072);
    transpose_cvt<<<dim3(24, 128, 4), dim3(32, 8)>>>(Vf, VTs);

    // scores: int8 corrections (2x rate) then fp16 hi-pass accumulate
    i8_gemm<true><<<dim3(32, 32, 4), 256, I8_SMEM>>>(q8h, k8l, sqh, skl, S);
    i8_gemm<false><<<dim3(32, 32, 4), 256, I8_SMEM>>>(q8l, k8h, sql, skh, S);
    wm_gemm<1, false, false, 2><<<dim3(32, 32, 4), 256, SMEM_TOTAL>>>(
        Qh, nullptr, Kh, nullptr, nullptr, S, nullptr, nullptr, nullptr, nullptr,
        4096, 768, 4096LL * 768, 4096LL * 768, 4096LL * 4096);

    softmax_pair<<<16384, 256>>>(S, Ph, Pl);

    // newV = P @ VT^T (2-pass, pair out)
    wm_gemm<2, false, false, 1><<<dim3(6, 32, 4), 256, SMEM_TOTAL>>>(
        Ph, Pl, VTs, nullptr, nullptr, nullptr, NVh, NVl, nullptr, nullptr,
        768, 4096, 4096LL * 4096, 768LL * 4096, 4096LL * 768);

    // H = relu(newV @ W1^T + b1) (2-pass, pair out)
    wm_gemm<2, true, true, 1><<<dim3(24, 128, 1), 256, SMEM_TOTAL>>>(
        NVh, NVl, W1s, nullptr, b1, nullptr, Hh, Hl, nullptr, nullptr,
        3072, 768, 0, 0, 0);

    // out = H @ W2^T + b2 (2-pass, fp32 out)
    wm_gemm<2, true, false, 0><<<dim3(6, 128, 1), 256, SMEM_TOTAL>>>(
        Hh, Hl, W2s, nullptr, b2, out, nullptr, nullptr, nullptr, nullptr,
        768, 3072, 0, 0, 0);
}

// round 10
// speedup vs baseline: 1.4543x; 1.0009x over previous
#include <cuda_runtime.h>
#include <cuda_fp16.h>
#include <stdint.h>

// ============================================================================
// GPT block, sm_100-safe mma.sync. fp16 split precision + int8 corrections.
//   QKV   : fused 3-pass fp16 GEMM (Q,K pair out; V fp32 out)
//   scores: S = q8h*k8l + q8l*k8h (int8 @2x rate, exact s32) + Qh*Kh (fp16)
//   attn@V, FFN1, FFN2 : 2-pass fp16 (A pair x B single)
// R9 fix: s8 A-fragment register order is row-block-fastest (same as fp16),
//         not k-seg-fastest. a1/a2 were swapped in R8.
// ============================================================================

typedef __half h16;

// ---------------- helpers ----------------
__device__ __forceinline__ uint32_t smem_u32(const void* p) {
    uint32_t a;
    asm("{ .reg .u64 t; cvta.to.shared.u64 t, %1; cvt.u32.u64 %0, t; }"
        : "=r"(a) : "l"(p));
    return a;
}
__device__ __forceinline__ void cp16(uint32_t saddr, const void* g) {
    asm volatile("cp.async.cg.shared.global [%0], [%1], 16;"
                 :: "r"(saddr), "l"(g) : "memory");
}
#define CP_COMMIT() asm volatile("cp.async.commit_group;" ::: "memory")
#define CP_WAIT1()  asm volatile("cp.async.wait_group 1;" ::: "memory")

__device__ __forceinline__ void ldsm4(uint32_t* r, uint32_t a) {
    asm volatile("ldmatrix.sync.aligned.m8n8.x4.shared.b16 {%0,%1,%2,%3}, [%4];"
                 : "=r"(r[0]), "=r"(r[1]), "=r"(r[2]), "=r"(r[3]) : "r"(a));
}
__device__ __forceinline__ void mma16816(float* c, const uint32_t* a,
                                         const uint32_t* b) {
    asm volatile(
        "mma.sync.aligned.m16n8k16.row.col.f32.f16.f16.f32 "
        "{%0,%1,%2,%3}, {%4,%5,%6,%7}, {%8,%9}, {%0,%1,%2,%3};"
        : "+f"(c[0]), "+f"(c[1]), "+f"(c[2]), "+f"(c[3])
        : "r"(a[0]), "r"(a[1]), "r"(a[2]), "r"(a[3]), "r"(b[0]), "r"(b[1]));
}
__device__ __forceinline__ void mma_s8(int* c, const uint32_t* a,
                                       const uint32_t* b) {
    asm volatile(
        "mma.sync.aligned.m16n8k32.row.col.s32.s8.s8.s32 "
        "{%0,%1,%2,%3}, {%4,%5,%6,%7}, {%8,%9}, {%0,%1,%2,%3};"
        : "+r"(c[0]), "+r"(c[1]), "+r"(c[2]), "+r"(c[3])
        : "r"(a[0]), "r"(a[1]), "r"(a[2]), "r"(a[3]), "r"(b[0]), "r"(b[1]));
}

// XOR swizzle: 16B chunk at (row, seg) of a 64B-row tile.
__device__ __forceinline__ uint32_t swz(int r, int s) {
    return (uint32_t)(r * 64 + ((s ^ ((r >> 1) & 3)) << 4));
}
__device__ __forceinline__ void split2h(float v, h16& h, h16& l) {
    h = __float2half(v);
    l = __float2half(v - __half2float(h));
}

// ---------------- scratch ----------------
__device__ h16 g_Xh[16384LL * 768], g_Xl[16384LL * 768];
__device__ h16 g_Wch[2304LL * 768], g_Wcl[2304LL * 768];   // fused QKV weights
__device__ h16 g_W1s[3072 * 768];
__device__ h16 g_W2s[768 * 3072];
__device__ h16 g_Qh[4LL * 4096 * 768], g_Ql[4LL * 4096 * 768];
__device__ h16 g_Kh[4LL * 4096 * 768], g_Kl[4LL * 4096 * 768];
__device__ float g_Vf[4LL * 4096 * 768];
__device__ h16 g_VTs[4LL * 768 * 4096];
__device__ float g_S[4LL * 4096 * 4096];
__device__ h16 g_Ph[4LL * 4096 * 4096], g_Pl[4LL * 4096 * 4096];
__device__ h16 g_NVh[4LL * 4096 * 768], g_NVl[4LL * 4096 * 768];
__device__ h16 g_Hh[16384LL * 3072], g_Hl[16384LL * 3072];
__device__ char g_q8h[16384LL * 768], g_q8l[16384LL * 768];
__device__ char g_k8h[16384LL * 768], g_k8l[16384LL * 768];
__device__ float g_sqh[16384], g_sql[16384], g_skh[16384], g_skl[16384];

// ---------------- fp16 GEMM ----------------
// stage: Ah@0, Al@8192, Bh@16384, Bl@24576 ; stride 32768; 3 stages (96KB)
static constexpr int STAGE_BYTES = 32768;
static constexpr int SMEM_TOTAL  = 3 * STAGE_BYTES;

// OM: 0 = f32 store, 1 = pair store, 2 = f32 accumulate, 3 = fused QKV route
template <int PASSES>
__device__ __forceinline__ void load_stage(
    uint32_t so, int tid,
    const h16* __restrict__ Ah, const h16* __restrict__ Al,
    const h16* __restrict__ Bh, const h16* __restrict__ Bl,
    long long k0, int K)
{
    const int r = tid & 127, h = tid >> 7;
#pragma unroll
    for (int u = 0; u < 2; ++u) {
        const uint32_t d = swz(r, h * 2 + u);
        const long long g = (long long)r * K + k0 + (h * 2 + u) * 8;
        cp16(so + d,         Ah + g);
        if (PASSES >= 2) cp16(so + 8192 + d, Al + g);
        cp16(so + 16384 + d, Bh + g);
        if (PASSES == 3)  cp16(so + 24576 + d, Bl + g);
    }
}

template <int PASSES, bool BIAS, bool RELU, int OM>
__global__ __launch_bounds__(256, 2)
void wm_gemm(const h16* __restrict__ Ahi, const h16* __restrict__ Alo,
             const h16* __restrict__ Bhi, const h16* __restrict__ Blo,
             const float* __restrict__ bias,
             float* __restrict__ Cf, h16* __restrict__ Chi, h16* __restrict__ Clo,
             h16* __restrict__ C2hi, h16* __restrict__ C2lo,
             const int N, const int K,
             const long long bA, const long long bB, const long long bC)
{
    extern __shared__ __align__(128) char smem[];
    const uint32_t sb = smem_u32(smem);
    const int tid = threadIdx.x;
    const int wid = tid >> 5, lane = tid & 31;
    const int wm = wid >> 1, wn = wid & 1;
    const int lj = lane >> 3, lr = lane & 7;

    const long long bm = (long long)blockIdx.y * 128;
    const long long bn = (long long)blockIdx.x * 128;

    const h16* Ah = Ahi + (long long)blockIdx.z * bA + bm * K;
    const h16* Al = (PASSES >= 2) ? (Alo + (long long)blockIdx.z * bA + bm * K) : nullptr;
    const h16* Bh = Bhi + (long long)blockIdx.z * bB + bn * K;
    const h16* Bl = (PASSES == 3) ? (Blo + (long long)blockIdx.z * bB + bn * K) : nullptr;

    float acc[2][8][4];
#pragma unroll
    for (int i = 0; i < 2; ++i)
#pragma unroll
        for (int j = 0; j < 8; ++j)
#pragma unroll
            for (int t = 0; t < 4; ++t) acc[i][j][t] = 0.0f;

    const int NC = K / 32;

    load_stage<PASSES>(sb, tid, Ah, Al, Bh, Bl, 0, K);
    CP_COMMIT();
    load_stage<PASSES>(sb + STAGE_BYTES, tid, Ah, Al, Bh, Bl, 32, K);
    CP_COMMIT();

    const int arow = wm * 32 + ((lj & 1) << 3) + lr;
    const int aseg = lj >> 1;
    const int brow = wn * 64 + ((lj >> 1) << 3) + lr;
    const int bseg = lj & 1;

    int buf = 0;
    for (int c = 0; c < NC; ++c) {
        CP_WAIT1();
        __syncthreads();
        if (c + 2 < NC) {
            int nb = buf + 2; if (nb >= 3) nb -= 3;
            load_stage<PASSES>(sb + nb * STAGE_BYTES, tid, Ah, Al, Bh, Bl,
                               (long long)(c + 2) * 32, K);
        }
        CP_COMMIT();

        const uint32_t bb = sb + buf * STAGE_BYTES;
#pragma unroll
        for (int ks = 0; ks < 2; ++ks) {
            uint32_t Afh[2][4], Afl[2][4];
#pragma unroll
            for (int mt = 0; mt < 2; ++mt) {
                const uint32_t off = swz(arow + mt * 16, ks * 2 + aseg);
                ldsm4(Afh[mt], bb + off);
                if (PASSES >= 2) ldsm4(Afl[mt], bb + 8192 + off);
            }
#pragma unroll
            for (int ntp = 0; ntp < 4; ++ntp) {
                const uint32_t off = swz(brow + ntp * 16, ks * 2 + bseg);
                uint32_t Bfh[4];
                ldsm4(Bfh, bb + 16384 + off);
                uint32_t Bfl[4];
                if (PASSES == 3) ldsm4(Bfl, bb + 24576 + off);
#pragma unroll
                for (int mt = 0; mt < 2; ++mt)
#pragma unroll
                    for (int h = 0; h < 2; ++h) {
                        float* cc = acc[mt][ntp * 2 + h];
                        mma16816(cc, Afh[mt], &Bfh[h * 2]);
                        if (PASSES >= 2) mma16816(cc, Afl[mt], &Bfh[h * 2]);
                        if (PASSES == 3) mma16816(cc, Afh[mt], &Bfl[h * 2]);
                    }
            }
        }
        ++buf; if (buf == 3) buf = 0;
    }

    // ---- epilogue ----
    const long long zC = (long long)blockIdx.z * bC;
    const int rbase = (int)bm + wm * 32 + (lane >> 2);
    const int seg   = (OM == 3) ? (int)(bn / 768) : 0;
    const int cbase = (OM == 3)
        ? ((int)bn - seg * 768 + wn * 64 + (lane & 3) * 2)
        : ((int)bn + wn * 64 + (lane & 3) * 2);
    const int cstride = (OM == 3) ? 768 : N;

#pragma unroll
    for (int mt = 0; mt < 2; ++mt)
#pragma unroll
        for (int nt = 0; nt < 8; ++nt) {
            const int col = cbase + nt * 8;
            float b0 = 0.f, b1 = 0.f;
            if (BIAS) { b0 = bias[(int)bn + wn * 64 + (lane & 3) * 2 + nt * 8];
                        b1 = bias[(int)bn + wn * 64 + (lane & 3) * 2 + nt * 8 + 1]; }
#pragma unroll
            for (int rh = 0; rh < 2; ++rh) {
                const int row = rbase + mt * 16 + rh * 8;
                float v0 = acc[mt][nt][rh * 2 + 0];
                float v1 = acc[mt][nt][rh * 2 + 1];
                if (BIAS) { v0 += b0; v1 += b1; }
                if (RELU) { v0 = fmaxf(v0, 0.f); v1 = fmaxf(v1, 0.f); }
                const long long o = zC + (long long)row * cstride + col;
                if (OM == 0) {
                    float2 w; w.x = v0; w.y = v1;
                    *(float2*)(Cf + o) = w;
                } else if (OM == 1) {
                    h16 h0, l0, h1, l1;
                    split2h(v0, h0, l0); split2h(v1, h1, l1);
                    *(__half2*)(Chi + o) = __halves2half2(h0, h1);
                    *(__half2*)(Clo + o) = __halves2half2(l0, l1);
                } else if (OM == 2) {
                    float2 t = *(const float2*)(Cf + o);
                    t.x += v0; t.y += v1;
                    *(float2*)(Cf + o) = t;
                } else {  // OM == 3: fused QKV routing
                    if (seg == 0) {
                        h16 h0, l0, h1, l1;
                        split2h(v0, h0, l0); split2h(v1, h1, l1);
                        *(__half2*)(Chi + o) = __halves2half2(h0, h1);
                        *(__half2*)(Clo + o) = __halves2half2(l0, l1);
                    } else if (seg == 1) {
                        h16 h0, l0, h1, l1;
                        split2h(v0, h0, l0); split2h(v1, h1, l1);
                        *(__half2*)(C2hi + o) = __halves2half2(h0, h1);
                        *(__half2*)(C2lo + o) = __halves2half2(l0, l1);
                    } else {
                        float2 w; w.x = v0; w.y = v1;
                        *(float2*)(Cf + o) = w;
                    }
                }
            }
        }
}

// ---------------- int8 correction GEMM: S (=/+=) (A8@B8^T) * sa_i * sb_j ------
// K=768 fixed, tiles 128x128, BK=64. stage: A@0 (8KB), B@8192; stride 16KB x3.
static constexpr int I8_STAGE = 16384;
static constexpr int I8_SMEM  = 3 * I8_STAGE;

__device__ __forceinline__ void i8_load_stage(uint32_t so, int tid,
    const char* __restrict__ A, const char* __restrict__ B, int k0)
{
    const int r = tid & 127, hf = tid >> 7;
#pragma unroll
    for (int u = 0; u < 2; ++u) {
        const int s = hf * 2 + u;
        const uint32_t d = swz(r, s);
        const long long g = (long long)r * 768 + k0 + s * 16;
        cp16(so + d,        A + g);
        cp16(so + 8192 + d, B + g);
    }
}

template <bool INIT>
__global__ __launch_bounds__(256, 2)
void i8_gemm(const char* __restrict__ A8, const char* __restrict__ B8,
             const float* __restrict__ sa, const float* __restrict__ sb,
             float* __restrict__ S)
{
    extern __shared__ __align__(128) char smem[];
    const uint32_t sbase = smem_u32(smem);
    const int tid = threadIdx.x;
    const int wid = tid >> 5, lane = tid & 31;
    const int wm = wid >> 1, wn = wid & 1;
    const int lj = lane >> 3, lr = lane & 7;
    const int z = blockIdx.z;
    const long long bm = (long long)blockIdx.y * 128;
    const long long bn = (long long)blockIdx.x * 128;

    const char* Ab = A8 + (long long)z * 4096 * 768 + bm * 768;
    const char* Bb = B8 + (long long)z * 4096 * 768 + bn * 768;
    const float* sav = sa + z * 4096 + bm;
    const float* sbv = sb + z * 4096 + bn;

    int acc[2][8][4];
#pragma unroll
    for (int i = 0; i < 2; ++i)
#pragma unroll
        for (int j = 0; j < 8; ++j)
#pragma unroll
            for (int t = 0; t < 4; ++t) acc[i][j][t] = 0;

    i8_load_stage(sbase, tid, Ab, Bb, 0);
    CP_COMMIT();
    i8_load_stage(sbase + I8_STAGE, tid, Ab, Bb, 64);
    CP_COMMIT();

    // s8 fragment order == fp16 order: row-block fastest for A (a0,a1 = row
    // g,g+8 k-first; a2,a3 = k-second); k-seg fastest for B pairs.
    const int arow = wm * 32 + ((lj & 1) << 3) + lr;
    const int aso  = lj >> 1;
    const int brow = wn * 64 + ((lj >> 1) << 3) + lr;
    const int bso  = lj & 1;

    int buf = 0;
    for (int c = 0; c < 12; ++c) {
        CP_WAIT1();
        __syncthreads();
        if (c + 2 < 12) {
            int nb = buf + 2; if (nb >= 3) nb -= 3;
            i8_load_stage(sbase + nb * I8_STAGE, tid, Ab, Bb, (c + 2) * 64);
        }
        CP_COMMIT();

        const uint32_t bb = sbase + buf * I8_STAGE;
#pragma unroll
        for (int step = 0; step < 2; ++step) {
            uint32_t Af[2][4];
#pragma unroll
            for (int mt = 0; mt < 2; ++mt)
                ldsm4(Af[mt], bb + swz(arow + mt * 16, step * 2 + aso));
#pragma unroll
            for (int ntp = 0; ntp < 4; ++ntp) {
                uint32_t Bf[4];
                ldsm4(Bf, bb + 8192 + swz(brow + ntp * 16, step * 2 + bso));
#pragma unroll
                for (int mt = 0; mt < 2; ++mt)
#pragma unroll
                    for (int h = 0; h < 2; ++h)
                        mma_s8(acc[mt][ntp * 2 + h], Af[mt], &Bf[h * 2]);
            }
        }
        ++buf; if (buf == 3) buf = 0;
    }

    // epilogue: scale + write/accumulate into S
    const int rb = wm * 32 + (lane >> 2);
    const int cb = wn * 64 + (lane & 3) * 2;
    const long long zS = (long long)z * 4096 * 4096;
#pragma unroll
    for (int mt = 0; mt < 2; ++mt)
#pragma unroll
        for (int rh = 0; rh < 2; ++rh) {
            const int lrw = rb + mt * 16 + rh * 8;
            const float sA = sav[lrw];
#pragma unroll
            for (int nt = 0; nt < 8; ++nt) {
                const int lc = cb + nt * 8;
                const float c0 = (float)acc[mt][nt][rh * 2 + 0] * sA * sbv[lc];
                const float c1 = (float)acc[mt][nt][rh * 2 + 1] * sA * sbv[lc + 1];
                const long long o = zS + (bm + lrw) * 4096 + bn + lc;
                if (INIT) {
                    float2 w; w.x = c0; w.y = c1;
                    *(float2*)(S + o) = w;
                } else {
                    float2 t = *(const float2*)(S + o);
                    t.x += c0; t.y += c1;
                    *(float2*)(S + o) = t;
                }
            }
        }
}

// ---------------- per-row int8 quantization of (hi,lo) fp16 pair ----------------
__global__ __launch_bounds__(256)
void quant_rows(const h16* __restrict__ Ah, const h16* __restrict__ Al,
                char* __restrict__ q8h, char* __restrict__ q8l,
                float* __restrict__ sh, float* __restrict__ sl)
{
    __shared__ float red[8][2];
    const long long row = blockIdx.x;
    const int tid = threadIdx.x, lane = tid & 31, warp = tid >> 5;
    const h16* ph = Ah + row * 768;
    const h16* pl = Al + row * 768;

    float vh[3], vl[3];
    float mh = 0.f, ml = 0.f;
#pragma unroll
    for (int i = 0; i < 3; ++i) {
        vh[i] = __half2float(ph[tid + i * 256]);
        vl[i] = __half2float(pl[tid + i * 256]);
        mh = fmaxf(mh, fabsf(vh[i]));
        ml = fmaxf(ml, fabsf(vl[i]));
    }
#pragma unroll
    for (int o = 16; o > 0; o >>= 1) {
        mh = fmaxf(mh, __shfl_xor_sync(0xffffffffu, mh, o));
        ml = fmaxf(ml, __shfl_xor_sync(0xffffffffu, ml, o));
    }
    if (lane == 0) { red[warp][0] = mh; red[warp][1] = ml; }
    __syncthreads();
    mh = red[0][0]; ml = red[0][1];
#pragma unroll
    for (int w = 1; w < 8; ++w) {
        mh = fmaxf(mh, red[w][0]);
        ml = fmaxf(ml, red[w][1]);
    }
    mh = fmaxf(mh, 1e-20f);
    ml = fmaxf(ml, 1e-20f);
    const float ih = 127.f / mh, il = 127.f / ml;
#pragma unroll
    for (int i = 0; i < 3; ++i) {
        q8h[row * 768 + tid + i * 256] = (char)__float2int_rn(vh[i] * ih);
        q8l[row * 768 + tid + i * 256] = (char)__float2int_rn(vl[i] * il);
    }
    if (tid == 0) { sh[row] = mh / 127.f; sl[row] = ml / 127.f; }
}

// ---------------- fp32 -> (hi,lo) fp16 ----------------
__global__ __launch_bounds__(256)
void cvt_pair(const float* __restrict__ in, h16* __restrict__ hi,
              h16* __restrict__ lo, const long long n)
{
    const long long i = ((long long)blockIdx.x * 256 + threadIdx.x) * 4;
    if (i >= n) return;
    const float4 v = *(const float4*)(in + i);
    __align__(8) h16 h[4];
    __align__(8) h16 l[4];
    split2h(v.x, h[0], l[0]); split2h(v.y, h[1], l[1]);
    split2h(v.z, h[2], l[2]); split2h(v.w, h[3], l[3]);
    *(uint2*)(hi + i) = *(const uint2*)h;
    *(uint2*)(lo + i) = *(const uint2*)l;
}

// ---------------- fp32 -> single fp16 ----------------
__global__ __launch_bounds__(256)
void cvt_single(const float* __restrict__ in, h16* __restrict__ s,
                const long long n)
{
    const long long i = ((long long)blockIdx.x * 256 + threadIdx.x) * 4;
    if (i >= n) return;
    const float4 v = *(const float4*)(in + i);
    __align__(8) h16 h[4];
    h[0] = __float2half(v.x); h[1] = __float2half(v.y);
    h[2] = __float2half(v.z); h[3] = __float2half(v.w);
    *(uint2*)(s + i) = *(const uint2*)h;
}

// ---------------- V transpose: [b,4096,768]f32 -> [b,768,4096] fp16 ----------
__global__ __launch_bounds__(256)
void transpose_cvt(const float* __restrict__ V, h16* __restrict__ Ts)
{
    __shared__ float tile[32][33];
    const int b = blockIdx.z;
    const int e0 = blockIdx.x * 32;
    const int t0 = blockIdx.y * 32;
    const float* Vb = V + (long long)b * 4096 * 768;
    h16* Tb = Ts + (long long)b * 768 * 4096;
    const int tx = threadIdx.x, ty = threadIdx.y;
#pragma unroll
    for (int j = 0; j < 32; j += 8)
        tile[ty + j][tx] = Vb[(long long)(t0 + ty + j) * 768 + e0 + tx];
    __syncthreads();
#pragma unroll
    for (int j = 0; j < 32; j += 8) {
        const long long o = (long long)(e0 + ty + j) * 4096 + t0 + tx;
        Tb[o] = __float2half(tile[tx][ty + j]);
    }
}

// ---------------- softmax (rows of 4096) -> (hi,lo) fp16 ----------------
__global__ __launch_bounds__(256)
void softmax_pair(const float* __restrict__ S, h16* __restrict__ Ph,
                  h16* __restrict__ Pl)
{
    __shared__ float red[8];
    const long long row = blockIdx.x;
    const float* p = S + row * 4096;
    const int tid = threadIdx.x, lane = tid & 31, warp = tid >> 5;

    float4 v[4];
#pragma unroll
    for (int i = 0; i < 4; ++i)
        v[i] = *(const float4*)(p + tid * 4 + i * 1024);

    float mx = -3.402823466e38f;
#pragma unroll
    for (int i = 0; i < 4; ++i)
        mx = fmaxf(mx, fmaxf(fmaxf(v[i].x, v[i].y), fmaxf(v[i].z, v[i].w)));
#pragma unroll
    for (int o = 16; o > 0; o >>= 1)
        mx = fmaxf(mx, __shfl_xor_sync(0xffffffffu, mx, o));
    if (lane == 0) red[warp] = mx;
    __syncthreads();
    float rowmax = red[0];
#pragma unroll
    for (int w = 1; w < 8; ++w) rowmax = fmaxf(rowmax, red[w]);
    __syncthreads();

    float sum = 0.0f;
#pragma unroll
    for (int i = 0; i < 4; ++i) {
        v[i].x = __expf(v[i].x - rowmax);
        v[i].y = __expf(v[i].y - rowmax);
        v[i].z = __expf(v[i].z - rowmax);
        v[i].w = __expf(v[i].w - rowmax);
        sum += (v[i].x + v[i].y) + (v[i].z + v[i].w);
    }
#pragma unroll
    for (int o = 16; o > 0; o >>= 1)
        sum += __shfl_xor_sync(0xffffffffu, sum, o);
    if (lane == 0) red[warp] = sum;
    __syncthreads();
    float rowsum = 0.0f;
#pragma unroll
    for (int w = 0; w < 8; ++w) rowsum += red[w];
    const float inv = 1.0f / rowsum;

#pragma unroll
    for (int i = 0; i < 4; ++i) {
        __align__(8) h16 h[4];
        __align__(8) h16 l[4];
        split2h(v[i].x * inv, h[0], l[0]);
        split2h(v[i].y * inv, h[1], l[1]);
        split2h(v[i].z * inv, h[2], l[2]);
        split2h(v[i].w * inv, h[3], l[3]);
        const long long o = row * 4096 + tid * 4 + i * 1024;
        *(uint2*)(Ph + o) = *(const uint2*)h;
        *(uint2*)(Pl + o) = *(const uint2*)l;
    }
}

// ---------------- host ----------------
extern "C" void kernel_launch(void* const* d_in, const int* in_sizes, int n_in,
                              void* d_out, int out_size)
{
    const float* X  = (const float*)d_in[0];
    const float* Wq = (const float*)d_in[1];
    const float* Wk = (const float*)d_in[2];
    const float* Wv = (const float*)d_in[3];
    const float* W1 = (const float*)d_in[4];
    const float* b1 = (const float*)d_in[5];
    const float* W2 = (const float*)d_in[6];
    const float* b2 = (const float*)d_in[7];
    float* out = (float*)d_out;

    h16 *Xh, *Xl, *Wch, *Wcl, *W1s, *W2s;
    h16 *Qh, *Ql, *Kh, *Kl, *VTs, *Ph, *Pl, *NVh, *NVl, *Hh, *Hl;
    float *Vf, *S, *sqh, *sql, *skh, *skl;
    char *q8h, *q8l, *k8h, *k8l;
    cudaGetSymbolAddress((void**)&Xh, g_Xh);    cudaGetSymbolAddress((void**)&Xl, g_Xl);
    cudaGetSymbolAddress((void**)&Wch, g_Wch);  cudaGetSymbolAddress((void**)&Wcl, g_Wcl);
    cudaGetSymbolAddress((void**)&W1s, g_W1s);  cudaGetSymbolAddress((void**)&W2s, g_W2s);
    cudaGetSymbolAddress((void**)&Qh, g_Qh);    cudaGetSymbolAddress((void**)&Ql, g_Ql);
    cudaGetSymbolAddress((void**)&Kh, g_Kh);    cudaGetSymbolAddress((void**)&Kl, g_Kl);
    cudaGetSymbolAddress((void**)&Vf, g_Vf);    cudaGetSymbolAddress((void**)&VTs, g_VTs);
    cudaGetSymbolAddress((void**)&S, g_S);
    cudaGetSymbolAddress((void**)&Ph, g_Ph);    cudaGetSymbolAddress((void**)&Pl, g_Pl);
    cudaGetSymbolAddress((void**)&NVh, g_NVh);  cudaGetSymbolAddress((void**)&NVl, g_NVl);
    cudaGetSymbolAddress((void**)&Hh, g_Hh);    cudaGetSymbolAddress((void**)&Hl, g_Hl);
    cudaGetSymbolAddress((void**)&q8h, g_q8h);  cudaGetSymbolAddress((void**)&q8l, g_q8l);
    cudaGetSymbolAddress((void**)&k8h, g_k8h);  cudaGetSymbolAddress((void**)&k8l, g_k8l);
    cudaGetSymbolAddress((void**)&sqh, g_sqh);  cudaGetSymbolAddress((void**)&sql, g_sql);
    cudaGetSymbolAddress((void**)&skh, g_skh);  cudaGetSymbolAddress((void**)&skl, g_skl);

    cudaFuncSetAttribute(wm_gemm<3, false, false, 3>,
                         cudaFuncAttributeMaxDynamicSharedMemorySize, SMEM_TOTAL);
    cudaFuncSetAttribute(wm_gemm<1, false, false, 2>,
                         cudaFuncAttributeMaxDynamicSharedMemorySize, SMEM_TOTAL);
    cudaFuncSetAttribute(wm_gemm<2, false, false, 1>,
                         cudaFuncAttributeMaxDynamicSharedMemorySize, SMEM_TOTAL);
    cudaFuncSetAttribute(wm_gemm<2, true, true, 1>,
                         cudaFuncAttributeMaxDynamicSharedMemorySize, SMEM_TOTAL);
    cudaFuncSetAttribute(wm_gemm<2, true, false, 0>,
                         cudaFuncAttributeMaxDynamicSharedMemorySize, SMEM_TOTAL);
    cudaFuncSetAttribute(i8_gemm<true>,
                         cudaFuncAttributeMaxDynamicSharedMemorySize, I8_SMEM);
    cudaFuncSetAttribute(i8_gemm<false>,
                         cudaFuncAttributeMaxDynamicSharedMemorySize, I8_SMEM);

    // splits
    cvt_pair<<<12288, 256>>>(X,  Xh,  Xl,  16384LL * 768);
    cvt_pair<<<576,  256>>>(Wq, Wch,              Wcl,              768LL * 768);
    cvt_pair<<<576,  256>>>(Wk, Wch + 768 * 768,  Wcl + 768 * 768,  768LL * 768);
    cvt_pair<<<576,  256>>>(Wv, Wch + 1536 * 768, Wcl + 1536 * 768, 768LL * 768);
    cvt_single<<<2304, 256>>>(W1, W1s, 3072LL * 768);

    // fused QKV: [16384,2304] = X @ Wcat^T ; Q,K pair out; V fp32 out
    wm_gemm<3, false, false, 3><<<dim3(18, 128, 1), 256, SMEM_TOTAL>>>(
        Xh, Xl, Wch, Wcl, nullptr, Vf, Qh, Ql, Kh, Kl, 2304, 768, 0, 0, 0);

    quant_rows<<<16384, 256>>>(Qh, Ql, q8h, q8l, sqh, sql);
    quant_rows<<<16384, 256>>>(Kh, Kl, k8h, k8l, skh, skl);
    cvt_single<<<2304, 256>>>(W2, W2s, 768LL * 3072);
    transpose_cvt<<<dim3(24, 128, 4), dim3(32, 8)>>>(Vf, VTs);

    // scores: int8 corrections (2x rate) then fp16 hi-pass accumulate
    i8_gemm<true><<<dim3(32, 32, 4), 256, I8_SMEM>>>(q8h, k8l, sqh, skl, S);
    i8_gemm<false><<<dim3(32, 32, 4), 256, I8_SMEM>>>(q8l, k8h, sql, skh, S);
    wm_gemm<1, false, false, 2><<<dim3(32, 32, 4), 256, SMEM_TOTAL>>>(
        Qh, nullptr, Kh, nullptr, nullptr, S, nullptr, nullptr, nullptr, nullptr,
        4096, 768, 4096LL * 768, 4096LL * 768, 4096LL * 4096);

    softmax_pair<<<16384, 256>>>(S, Ph, Pl);

    // newV = P @ VT^T (2-pass, pair out)
    wm_gemm<2, false, false, 1><<<dim3(6, 32, 4), 256, SMEM_TOTAL>>>(
        Ph, Pl, VTs, nullptr, nullptr, nullptr, NVh, NVl, nullptr, nullptr,
        768, 4096, 4096LL * 4096, 768LL * 4096, 4096LL * 768);

    // H = relu(newV @ W1^T + b1) (2-pass, pair out)
    wm_gemm<2, true, true, 1><<<dim3(24, 128, 1), 256, SMEM_TOTAL>>>(
        NVh, NVl, W1s, nullptr, b1, nullptr, Hh, Hl, nullptr, nullptr,
        3072, 768, 0, 0, 0);

    // out = H @ W2^T + b2 (2-pass, fp32 out)
    wm_gemm<2, true, false, 0><<<dim3(6, 128, 1), 256, SMEM_TOTAL>>>(
        Hh, Hl, W2s, nullptr, b2, out, nullptr, nullptr, nullptr, nullptr,
        768, 3072, 0, 0, 0);
}

// round 11
// speedup vs baseline: 1.4553x; 1.0007x over previous
#include <cuda_runtime.h>
#include <cuda_fp16.h>
#include <stdint.h>

// ============================================================================
// GPT block, sm_100-safe mma.sync. fp16 split precision + int8 corrections.
//   QKV   : fused 3-pass fp16 GEMM (Q,K pair out; V fp32 out)
//   scores: S = q8h*k8l + q8l*k8h (int8 @2x rate, exact s32) + Qh*Kh (fp16)
//   attn@V, FFN1, FFN2 : 2-pass fp16 (A pair x B single)
// R9 fix: s8 A-fragment register order is row-block-fastest (same as fp16),
//         not k-seg-fastest. a1/a2 were swapped in R8.
// ============================================================================

typedef __half h16;

// ---------------- helpers ----------------
__device__ __forceinline__ uint32_t smem_u32(const void* p) {
    uint32_t a;
    asm("{ .reg .u64 t; cvta.to.shared.u64 t, %1; cvt.u32.u64 %0, t; }"
        : "=r"(a) : "l"(p));
    return a;
}
__device__ __forceinline__ void cp16(uint32_t saddr, const void* g) {
    asm volatile("cp.async.cg.shared.global [%0], [%1], 16;"
                 :: "r"(saddr), "l"(g) : "memory");
}
#define CP_COMMIT() asm volatile("cp.async.commit_group;" ::: "memory")
#define CP_WAIT1()  asm volatile("cp.async.wait_group 1;" ::: "memory")

__device__ __forceinline__ void ldsm4(uint32_t* r, uint32_t a) {
    asm volatile("ldmatrix.sync.aligned.m8n8.x4.shared.b16 {%0,%1,%2,%3}, [%4];"
                 : "=r"(r[0]), "=r"(r[1]), "=r"(r[2]), "=r"(r[3]) : "r"(a));
}
__device__ __forceinline__ void mma16816(float* c, const uint32_t* a,
                                         const uint32_t* b) {
    asm volatile(
        "mma.sync.aligned.m16n8k16.row.col.f32.f16.f16.f32 "
        "{%0,%1,%2,%3}, {%4,%5,%6,%7}, {%8,%9}, {%0,%1,%2,%3};"
        : "+f"(c[0]), "+f"(c[1]), "+f"(c[2]), "+f"(c[3])
        : "r"(a[0]), "r"(a[1]), "r"(a[2]), "r"(a[3]), "r"(b[0]), "r"(b[1]));
}
__device__ __forceinline__ void mma_s8(int* c, const uint32_t* a,
                                       const uint32_t* b) {
    asm volatile(
        "mma.sync.aligned.m16n8k32.row.col.s32.s8.s8.s32 "
        "{%0,%1,%2,%3}, {%4,%5,%6,%7}, {%8,%9}, {%0,%1,%2,%3};"
        : "+r"(c[0]), "+r"(c[1]), "+r"(c[2]), "+r"(c[3])
        : "r"(a[0]), "r"(a[1]), "r"(a[2]), "r"(a[3]), "r"(b[0]), "r"(b[1]));
}

// XOR swizzle: 16B chunk at (row, seg) of a 64B-row tile.
__device__ __forceinline__ uint32_t swz(int r, int s) {
    return (uint32_t)(r * 64 + ((s ^ ((r >> 1) & 3)) << 4));
}
__device__ __forceinline__ void split2h(float v, h16& h, h16& l) {
    h = __float2half(v);
    l = __float2half(v - __half2float(h));
}

// ---------------- scratch ----------------
__device__ h16 g_Xh[16384LL * 768], g_Xl[16384LL * 768];
__device__ h16 g_Wch[2304LL * 768], g_Wcl[2304LL * 768];   // fused QKV weights
__device__ h16 g_W1s[3072 * 768];
__device__ h16 g_W2s[768 * 3072];
__device__ h16 g_Qh[4LL * 4096 * 768], g_Ql[4LL * 4096 * 768];
__device__ h16 g_Kh[4LL * 4096 * 768], g_Kl[4LL * 4096 * 768];
__device__ float g_Vf[4LL * 4096 * 768];
__device__ h16 g_VTs[4LL * 768 * 4096];
__device__ float g_S[4LL * 4096 * 4096];
__device__ h16 g_Ph[4LL * 4096 * 4096], g_Pl[4LL * 4096 * 4096];
__device__ h16 g_NVh[4LL * 4096 * 768], g_NVl[4LL * 4096 * 768];
__device__ h16 g_Hh[16384LL * 3072], g_Hl[16384LL * 3072];
__device__ char g_q8h[16384LL * 768], g_q8l[16384LL * 768];
__device__ char g_k8h[16384LL * 768], g_k8l[16384LL * 768];
__device__ float g_sqh[16384], g_sql[16384], g_skh[16384], g_skl[16384];

// ---------------- fp16 GEMM ----------------
// stage: Ah@0, Al@8192, Bh@16384, Bl@24576 ; stride 32768; 3 stages (96KB)
static constexpr int STAGE_BYTES = 32768;
static constexpr int SMEM_TOTAL  = 3 * STAGE_BYTES;

// OM: 0 = f32 store, 1 = pair store, 2 = f32 accumulate, 3 = fused QKV route
template <int PASSES>
__device__ __forceinline__ void load_stage(
    uint32_t so, int tid,
    const h16* __restrict__ Ah, const h16* __restrict__ Al,
    const h16* __restrict__ Bh, const h16* __restrict__ Bl,
    long long k0, int K)
{
    const int r = tid & 127, h = tid >> 7;
#pragma unroll
    for (int u = 0; u < 2; ++u) {
        const uint32_t d = swz(r, h * 2 + u);
        const long long g = (long long)r * K + k0 + (h * 2 + u) * 8;
        cp16(so + d,         Ah + g);
        if (PASSES >= 2) cp16(so + 8192 + d, Al + g);
        cp16(so + 16384 + d, Bh + g);
        if (PASSES == 3)  cp16(so + 24576 + d, Bl + g);
    }
}

template <int PASSES, bool BIAS, bool RELU, int OM>
__global__ __launch_bounds__(256, 2)
void wm_gemm(const h16* __restrict__ Ahi, const h16* __restrict__ Alo,
             const h16* __restrict__ Bhi, const h16* __restrict__ Blo,
             const float* __restrict__ bias,
             float* __restrict__ Cf, h16* __restrict__ Chi, h16* __restrict__ Clo,
             h16* __restrict__ C2hi, h16* __restrict__ C2lo,
             const int N, const int K,
             const long long bA, const long long bB, const long long bC)
{
    extern __shared__ __align__(128) char smem[];
    const uint32_t sb = smem_u32(smem);
    const int tid = threadIdx.x;
    const int wid = tid >> 5, lane = tid & 31;
    const int wm = wid >> 1, wn = wid & 1;
    const int lj = lane >> 3, lr = lane & 7;

    const long long bm = (long long)blockIdx.y * 128;
    const long long bn = (long long)blockIdx.x * 128;

    const h16* Ah = Ahi + (long long)blockIdx.z * bA + bm * K;
    const h16* Al = (PASSES >= 2) ? (Alo + (long long)blockIdx.z * bA + bm * K) : nullptr;
    const h16* Bh = Bhi + (long long)blockIdx.z * bB + bn * K;
    const h16* Bl = (PASSES == 3) ? (Blo + (long long)blockIdx.z * bB + bn * K) : nullptr;

    float acc[2][8][4];
#pragma unroll
    for (int i = 0; i < 2; ++i)
#pragma unroll
        for (int j = 0; j < 8; ++j)
#pragma unroll
            for (int t = 0; t < 4; ++t) acc[i][j][t] = 0.0f;

    const int NC = K / 32;

    load_stage<PASSES>(sb, tid, Ah, Al, Bh, Bl, 0, K);
    CP_COMMIT();
    load_stage<PASSES>(sb + STAGE_BYTES, tid, Ah, Al, Bh, Bl, 32, K);
    CP_COMMIT();

    const int arow = wm * 32 + ((lj & 1) << 3) + lr;
    const int aseg = lj >> 1;
    const int brow = wn * 64 + ((lj >> 1) << 3) + lr;
    const int bseg = lj & 1;

    int buf = 0;
    for (int c = 0; c < NC; ++c) {
        CP_WAIT1();
        __syncthreads();
        if (c + 2 < NC) {
            int nb = buf + 2; if (nb >= 3) nb -= 3;
            load_stage<PASSES>(sb + nb * STAGE_BYTES, tid, Ah, Al, Bh, Bl,
                               (long long)(c + 2) * 32, K);
        }
        CP_COMMIT();

        const uint32_t bb = sb + buf * STAGE_BYTES;
#pragma unroll
        for (int ks = 0; ks < 2; ++ks) {
            uint32_t Afh[2][4], Afl[2][4];
#pragma unroll
            for (int mt = 0; mt < 2; ++mt) {
                const uint32_t off = swz(arow + mt * 16, ks * 2 + aseg);
                ldsm4(Afh[mt], bb + off);
                if (PASSES >= 2) ldsm4(Afl[mt], bb + 8192 + off);
            }
#pragma unroll
            for (int ntp = 0; ntp < 4; ++ntp) {
                const uint32_t off = swz(brow + ntp * 16, ks * 2 + bseg);
                uint32_t Bfh[4];
                ldsm4(Bfh, bb + 16384 + off);
                uint32_t Bfl[4];
                if (PASSES == 3) ldsm4(Bfl, bb + 24576 + off);
#pragma unroll
                for (int mt = 0; mt < 2; ++mt)
#pragma unroll
                    for (int h = 0; h < 2; ++h) {
                        float* cc = acc[mt][ntp * 2 + h];
                        mma16816(cc, Afh[mt], &Bfh[h * 2]);
                        if (PASSES >= 2) mma16816(cc, Afl[mt], &Bfh[h * 2]);
                        if (PASSES == 3) mma16816(cc, Afh[mt], &Bfl[h * 2]);
                    }
            }
        }
        ++buf; if (buf == 3) buf = 0;
    }

    // ---- epilogue ----
    const long long zC = (long long)blockIdx.z * bC;
    const int rbase = (int)bm + wm * 32 + (lane >> 2);
    const int seg   = (OM == 3) ? (int)(bn / 768) : 0;
    const int cbase = (OM == 3)
        ? ((int)bn - seg * 768 + wn * 64 + (lane & 3) * 2)
        : ((int)bn + wn * 64 + (lane & 3) * 2);
    const int cstride = (OM == 3) ? 768 : N;

#pragma unroll
    for (int mt = 0; mt < 2; ++mt)
#pragma unroll
        for (int nt = 0; nt < 8; ++nt) {
            const int col = cbase + nt * 8;
            float b0 = 0.f, b1 = 0.f;
            if (BIAS) { b0 = bias[(int)bn + wn * 64 + (lane & 3) * 2 + nt * 8];
                        b1 = bias[(int)bn + wn * 64 + (lane & 3) * 2 + nt * 8 + 1]; }
#pragma unroll
            for (int rh = 0; rh < 2; ++rh) {
                const int row = rbase + mt * 16 + rh * 8;
                float v0 = acc[mt][nt][rh * 2 + 0];
                float v1 = acc[mt][nt][rh * 2 + 1];
                if (BIAS) { v0 += b0; v1 += b1; }
                if (RELU) { v0 = fmaxf(v0, 0.f); v1 = fmaxf(v1, 0.f); }
                const long long o = zC + (long long)row * cstride + col;
                if (OM == 0) {
                    float2 w; w.x = v0; w.y = v1;
                    *(float2*)(Cf + o) = w;
                } else if (OM == 1) {
                    h16 h0, l0, h1, l1;
                    split2h(v0, h0, l0); split2h(v1, h1, l1);
                    *(__half2*)(Chi + o) = __halves2half2(h0, h1);
                    *(__half2*)(Clo + o) = __halves2half2(l0, l1);
                } else if (OM == 2) {
                    float2 t = *(const float2*)(Cf + o);
                    t.x += v0; t.y += v1;
                    *(float2*)(Cf + o) = t;
                } else {  // OM == 3: fused QKV routing
                    if (seg == 0) {
                        h16 h0, l0, h1, l1;
                        split2h(v0, h0, l0); split2h(v1, h1, l1);
                        *(__half2*)(Chi + o) = __halves2half2(h0, h1);
                        *(__half2*)(Clo + o) = __halves2half2(l0, l1);
                    } else if (seg == 1) {
                        h16 h0, l0, h1, l1;
                        split2h(v0, h0, l0); split2h(v1, h1, l1);
                        *(__half2*)(C2hi + o) = __halves2half2(h0, h1);
                        *(__half2*)(C2lo + o) = __halves2half2(l0, l1);
                    } else {
                        float2 w; w.x = v0; w.y = v1;
                        *(float2*)(Cf + o) = w;
                    }
                }
            }
        }
}

// ---------------- int8 correction GEMM: S (=/+=) (A8@B8^T) * sa_i * sb_j ------
// K=768 fixed, tiles 128x128, BK=64. stage: A@0 (8KB), B@8192; stride 16KB x3.
static constexpr int I8_STAGE = 16384;
static constexpr int I8_SMEM  = 3 * I8_STAGE;

__device__ __forceinline__ void i8_load_stage(uint32_t so, int tid,
    const char* __restrict__ A, const char* __restrict__ B, int k0)
{
    const int r = tid & 127, hf = tid >> 7;
#pragma unroll
    for (int u = 0; u < 2; ++u) {
        const int s = hf * 2 + u;
        const uint32_t d = swz(r, s);
        const long long g = (long long)r * 768 + k0 + s * 16;
        cp16(so + d,        A + g);
        cp16(so + 8192 + d, B + g);
    }
}

template <bool INIT>
__global__ __launch_bounds__(256, 2)
void i8_gemm(const char* __restrict__ A8, const char* __restrict__ B8,
             const float* __restrict__ sa, const float* __restrict__ sb,
             float* __restrict__ S)
{
    extern __shared__ __align__(128) char smem[];
    const uint32_t sbase = smem_u32(smem);
    const int tid = threadIdx.x;
    const int wid = tid >> 5, lane = tid & 31;
    const int wm = wid >> 1, wn = wid & 1;
    const int lj = lane >> 3, lr = lane & 7;
    const int z = blockIdx.z;
    const long long bm = (long long)blockIdx.y * 128;
    const long long bn = (long long)blockIdx.x * 128;

    const char* Ab = A8 + (long long)z * 4096 * 768 + bm * 768;
    const char* Bb = B8 + (long long)z * 4096 * 768 + bn * 768;
    const float* sav = sa + z * 4096 + bm;
    const float* sbv = sb + z * 4096 + bn;

    int acc[2][8][4];
#pragma unroll
    for (int i = 0; i < 2; ++i)
#pragma unroll
        for (int j = 0; j < 8; ++j)
#pragma unroll
            for (int t = 0; t < 4; ++t) acc[i][j][t] = 0;

    i8_load_stage(sbase, tid, Ab, Bb, 0);
    CP_COMMIT();
    i8_load_stage(sbase + I8_STAGE, tid, Ab, Bb, 64);
    CP_COMMIT();

    // s8 fragment order == fp16 order: row-block fastest for A (a0,a1 = row
    // g,g+8 k-first; a2,a3 = k-second); k-seg fastest for B pairs.
    const int arow = wm * 32 + ((lj & 1) << 3) + lr;
    const int aso  = lj >> 1;
    const int brow = wn * 64 + ((lj >> 1) << 3) + lr;
    const int bso  = lj & 1;

    int buf = 0;
    for (int c = 0; c < 12; ++c) {
        CP_WAIT1();
        __syncthreads();
        if (c + 2 < 12) {
            int nb = buf + 2; if (nb >= 3) nb -= 3;
            i8_load_stage(sbase + nb * I8_STAGE, tid, Ab, Bb, (c + 2) * 64);
        }
        CP_COMMIT();

        const uint32_t bb = sbase + buf * I8_STAGE;
#pragma unroll
        for (int step = 0; step < 2; ++step) {
            uint32_t Af[2][4];
#pragma unroll
            for (int mt = 0; mt < 2; ++mt)
                ldsm4(Af[mt], bb + swz(arow + mt * 16, step * 2 + aso));
#pragma unroll
            for (int ntp = 0; ntp < 4; ++ntp) {
                uint32_t Bf[4];
                ldsm4(Bf, bb + 8192 + swz(brow + ntp * 16, step * 2 + bso));
#pragma unroll
                for (int mt = 0; mt < 2; ++mt)
#pragma unroll
                    for (int h = 0; h < 2; ++h)
                        mma_s8(acc[mt][ntp * 2 + h], Af[mt], &Bf[h * 2]);
            }
        }
        ++buf; if (buf == 3) buf = 0;
    }

    // epilogue: scale + write/accumulate into S
    const int rb = wm * 32 + (lane >> 2);
    const int cb = wn * 64 + (lane & 3) * 2;
    const long long zS = (long long)z * 4096 * 4096;
#pragma unroll
    for (int mt = 0; mt < 2; ++mt)
#pragma unroll
        for (int rh = 0; rh < 2; ++rh) {
            const int lrw = rb + mt * 16 + rh * 8;
            const float sA = sav[lrw];
#pragma unroll
            for (int nt = 0; nt < 8; ++nt) {
                const int lc = cb + nt * 8;
                const float c0 = (float)acc[mt][nt][rh * 2 + 0] * sA * sbv[lc];
                const float c1 = (float)acc[mt][nt][rh * 2 + 1] * sA * sbv[lc + 1];
                const long long o = zS + (bm + lrw) * 4096 + bn + lc;
                if (INIT) {
                    float2 w; w.x = c0; w.y = c1;
                    *(float2*)(S + o) = w;
                } else {
                    float2 t = *(const float2*)(S + o);
                    t.x += c0; t.y += c1;
                    *(float2*)(S + o) = t;
                }
            }
        }
}

// ---------------- per-row int8 quantization of (hi,lo) fp16 pair ----------------
__global__ __launch_bounds__(256)
void quant_rows(const h16* __restrict__ Ah, const h16* __restrict__ Al,
                char* __restrict__ q8h, char* __restrict__ q8l,
                float* __restrict__ sh, float* __restrict__ sl)
{
    __shared__ float red[8][2];
    const long long row = blockIdx.x;
    const int tid = threadIdx.x, lane = tid & 31, warp = tid >> 5;
    const h16* ph = Ah + row * 768;
    const h16* pl = Al + row * 768;

    float vh[3], vl[3];
    float mh = 0.f, ml = 0.f;
#pragma unroll
    for (int i = 0; i < 3; ++i) {
        vh[i] = __half2float(ph[tid + i * 256]);
        vl[i] = __half2float(pl[tid + i * 256]);
        mh = fmaxf(mh, fabsf(vh[i]));
        ml = fmaxf(ml, fabsf(vl[i]));
    }
#pragma unroll
    for (int o = 16; o > 0; o >>= 1) {
        mh = fmaxf(mh, __shfl_xor_sync(0xffffffffu, mh, o));
        ml = fmaxf(ml, __shfl_xor_sync(0xffffffffu, ml, o));
    }
    if (lane == 0) { red[warp][0] = mh; red[warp][1] = ml; }
    __syncthreads();
    mh = red[0][0]; ml = red[0][1];
#pragma unroll
    for (int w = 1; w < 8; ++w) {
        mh = fmaxf(mh, red[w][0]);
        ml = fmaxf(ml, red[w][1]);
    }
    mh = fmaxf(mh, 1e-20f);
    ml = fmaxf(ml, 1e-20f);
    const float ih = 127.f / mh, il = 127.f / ml;
#pragma unroll
    for (int i = 0; i < 3; ++i) {
        q8h[row * 768 + tid + i * 256] = (char)__float2int_rn(vh[i] * ih);
        q8l[row * 768 + tid + i * 256] = (char)__float2int_rn(vl[i] * il);
    }
    if (tid == 0) { sh[row] = mh / 127.f; sl[row] = ml / 127.f; }
}

// ---------------- fp32 -> (hi,lo) fp16 ----------------
__global__ __launch_bounds__(256)
void cvt_pair(const float* __restrict__ in, h16* __restrict__ hi,
              h16* __restrict__ lo, const long long n)
{
    const long long i = ((long long)blockIdx.x * 256 + threadIdx.x) * 4;
    if (i >= n) return;
    const float4 v = *(const float4*)(in + i);
    __align__(8) h16 h[4];
    __align__(8) h16 l[4];
    split2h(v.x, h[0], l[0]); split2h(v.y, h[1], l[1]);
    split2h(v.z, h[2], l[2]); split2h(v.w, h[3], l[3]);
    *(uint2*)(hi + i) = *(const uint2*)h;
    *(uint2*)(lo + i) = *(const uint2*)l;
}

// ---------------- fp32 -> single fp16 ----------------
__global__ __launch_bounds__(256)
void cvt_single(const float* __restrict__ in, h16* __restrict__ s,
                const long long n)
{
    const long long i = ((long long)blockIdx.x * 256 + threadIdx.x) * 4;
    if (i >= n) return;
    const float4 v = *(const float4*)(in + i);
    __align__(8) h16 h[4];
    h[0] = __float2half(v.x); h[1] = __float2half(v.y);
    h[2] = __float2half(v.z); h[3] = __float2half(v.w);
    *(uint2*)(s + i) = *(const uint2*)h;
}

// ---------------- V transpose: [b,4096,768]f32 -> [b,768,4096] fp16 ----------
__global__ __launch_bounds__(256)
void transpose_cvt(const float* __restrict__ V, h16* __restrict__ Ts)
{
    __shared__ float tile[32][33];
    const int b = blockIdx.z;
    const int e0 = blockIdx.x * 32;
    const int t0 = blockIdx.y * 32;
    const float* Vb = V + (long long)b * 4096 * 768;
    h16* Tb = Ts + (long long)b * 768 * 4096;
    const int tx = threadIdx.x, ty = threadIdx.y;
#pragma unroll
    for (int j = 0; j < 32; j += 8)
        tile[ty + j][tx] = Vb[(long long)(t0 + ty + j) * 768 + e0 + tx];
    __syncthreads();
#pragma unroll
    for (int j = 0; j < 32; j += 8) {
        const long long o = (long long)(e0 + ty + j) * 4096 + t0 + tx;
        Tb[o] = __float2half(tile[tx][ty + j]);
    }
}

// ---------------- softmax (rows of 4096) -> (hi,lo) fp16 ----------------
__global__ __launch_bounds__(256)
void softmax_pair(const float* __restrict__ S, h16* __restrict__ Ph,
                  h16* __restrict__ Pl)
{
    __shared__ float red[8];
    const long long row = blockIdx.x;
    const float* p = S + row * 4096;
    const int tid = threadIdx.x, lane = tid & 31, warp = tid >> 5;

    float4 v[4];
#pragma unroll
    for (int i = 0; i < 4; ++i)
        v[i] = *(const float4*)(p + tid * 4 + i * 1024);

    float mx = -3.402823466e38f;
#pragma unroll
    for (int i = 0; i < 4; ++i)
        mx = fmaxf(mx, fmaxf(fmaxf(v[i].x, v[i].y), fmaxf(v[i].z, v[i].w)));
#pragma unroll
    for (int o = 16; o > 0; o >>= 1)
        mx = fmaxf(mx, __shfl_xor_sync(0xffffffffu, mx, o));
    if (lane == 0) red[warp] = mx;
    __syncthreads();
    float rowmax = red[0];
#pragma unroll
    for (int w = 1; w < 8; ++w) rowmax = fmaxf(rowmax, red[w]);
    __syncthreads();

    float sum = 0.0f;
#pragma unroll
    for (int i = 0; i < 4; ++i) {
        v[i].x = __expf(v[i].x - rowmax);
        v[i].y = __expf(v[i].y - rowmax);
        v[i].z = __expf(v[i].z - rowmax);
        v[i].w = __expf(v[i].w - rowmax);
        sum += (v[i].x + v[i].y) + (v[i].z + v[i].w);
    }
#pragma unroll
    for (int o = 16; o > 0; o >>= 1)
        sum += __shfl_xor_sync(0xffffffffu, sum, o);
    if (lane == 0) red[warp] = sum;
    __syncthreads();
    float rowsum = 0.0f;
#pragma unroll
    for (int w = 0; w < 8; ++w) rowsum += red[w];
    const float inv = 1.0f / rowsum;

#pragma unroll
    for (int i = 0; i < 4; ++i) {
        __align__(8) h16 h[4];
        __align__(8) h16 l[4];
        split2h(v[i].x * inv, h[0], l[0]);
        split2h(v[i].y * inv, h[1], l[1]);
        split2h(v[i].z * inv, h[2], l[2]);
        split2h(v[i].w * inv, h[3], l[3]);
        const long long o = row * 4096 + tid * 4 + i * 1024;
        *(uint2*)(Ph + o) = *(const uint2*)h;
        *(uint2*)(Pl + o) = *(const uint2*)l;
    }
}

// ---------------- host ----------------
extern "C" void kernel_launch(void* const* d_in, const int* in_sizes, int n_in,
                              void* d_out, int out_size)
{
    const float* X  = (const float*)d_in[0];
    const float* Wq = (const float*)d_in[1];
    const float* Wk = (const float*)d_in[2];
    const float* Wv = (const float*)d_in[3];
    const float* W1 = (const float*)d_in[4];
    const float* b1 = (const float*)d_in[5];
    const float* W2 = (const float*)d_in[6];
    const float* b2 = (const float*)d_in[7];
    float* out = (float*)d_out;

    h16 *Xh, *Xl, *Wch, *Wcl, *W1s, *W2s;
    h16 *Qh, *Ql, *Kh, *Kl, *VTs, *Ph, *Pl, *NVh, *NVl, *Hh, *Hl;
    float *Vf, *S, *sqh, *sql, *skh, *skl;
    char *q8h, *q8l, *k8h, *k8l;
    cudaGetSymbolAddress((void**)&Xh, g_Xh);    cudaGetSymbolAddress((void**)&Xl, g_Xl);
    cudaGetSymbolAddress((void**)&Wch, g_Wch);  cudaGetSymbolAddress((void**)&Wcl, g_Wcl);
    cudaGetSymbolAddress((void**)&W1s, g_W1s);  cudaGetSymbolAddress((void**)&W2s, g_W2s);
    cudaGetSymbolAddress((void**)&Qh, g_Qh);    cudaGetSymbolAddress((void**)&Ql, g_Ql);
    cudaGetSymbolAddress((void**)&Kh, g_Kh);    cudaGetSymbolAddress((void**)&Kl, g_Kl);
    cudaGetSymbolAddress((void**)&Vf, g_Vf);    cudaGetSymbolAddress((void**)&VTs, g_VTs);
    cudaGetSymbolAddress((void**)&S, g_S);
    cudaGetSymbolAddress((void**)&Ph, g_Ph);    cudaGetSymbolAddress((void**)&Pl, g_Pl);
    cudaGetSymbolAddress((void**)&NVh, g_NVh);  cudaGetSymbolAddress((void**)&NVl, g_NVl);
    cudaGetSymbolAddress((void**)&Hh, g_Hh);    cudaGetSymbolAddress((void**)&Hl, g_Hl);
    cudaGetSymbolAddress((void**)&q8h, g_q8h);  cudaGetSymbolAddress((void**)&q8l, g_q8l);
    cudaGetSymbolAddress((void**)&k8h, g_k8h);  cudaGetSymbolAddress((void**)&k8l, g_k8l);
    cudaGetSymbolAddress((void**)&sqh, g_sqh);  cudaGetSymbolAddress((void**)&sql, g_sql);
    cudaGetSymbolAddress((void**)&skh, g_skh);  cudaGetSymbolAddress((void**)&skl, g_skl);

    cudaFuncSetAttribute(wm_gemm<3, false, false, 3>,
                         cudaFuncAttributeMaxDynamicSharedMemorySize, SMEM_TOTAL);
    cudaFuncSetAttribute(wm_gemm<1, false, false, 2>,
                         cudaFuncAttributeMaxDynamicSharedMemorySize, SMEM_TOTAL);
    cudaFuncSetAttribute(wm_gemm<2, false, false, 1>,
                         cudaFuncAttributeMaxDynamicSharedMemorySize, SMEM_TOTAL);
    cudaFuncSetAttribute(wm_gemm<2, true, true, 1>,
                         cudaFuncAttributeMaxDynamicSharedMemorySize, SMEM_TOTAL);
    cudaFuncSetAttribute(wm_gemm<2, true, false, 0>,
                         cudaFuncAttributeMaxDynamicSharedMemorySize, SMEM_TOTAL);
    cudaFuncSetAttribute(i8_gemm<true>,
                         cudaFuncAttributeMaxDynamicSharedMemorySize, I8_SMEM);
    cudaFuncSetAttribute(i8_gemm<false>,
                         cudaFuncAttributeMaxDynamicSharedMemorySize, I8_SMEM);

    // splits
    cvt_pair<<<12288, 256>>>(X,  Xh,  Xl,  16384LL * 768);
    cvt_pair<<<576,  256>>>(Wq, Wch,              Wcl,              768LL * 768);
    cvt_pair<<<576,  256>>>(Wk, Wch + 768 * 768,  Wcl + 768 * 768,  768LL * 768);
    cvt_pair<<<576,  256>>>(Wv, Wch + 1536 * 768, Wcl + 1536 * 768, 768LL * 768);
    cvt_single<<<2304, 256>>>(W1, W1s, 3072LL * 768);

    // fused QKV: [16384,2304] = X @ Wcat^T ; Q,K pair out; V fp32 out
    wm_gemm<3, false, false, 3><<<dim3(18, 128, 1), 256, SMEM_TOTAL>>>(
        Xh, Xl, Wch, Wcl, nullptr, Vf, Qh, Ql, Kh, Kl, 2304, 768, 0, 0, 0);

    quant_rows<<<16384, 256>>>(Qh, Ql, q8h, q8l, sqh, sql);
    quant_rows<<<16384, 256>>>(Kh, Kl, k8h, k8l, skh, skl);
    cvt_single<<<2304, 256>>>(W2, W2s, 768LL * 3072);
    transpose_cvt<<<dim3(24, 128, 4), dim3(32, 8)>>>(Vf, VTs);

    // scores: int8 corrections (2x rate) then fp16 hi-pass accumulate
    i8_gemm<true><<<dim3(32, 32, 4), 256, I8_SMEM>>>(q8h, k8l, sqh, skl, S);
    i8_gemm<false><<<dim3(32, 32, 4), 256, I8_SMEM>>>(q8l, k8h, sql, skh, S);
    wm_gemm<1, false, false, 2><<<dim3(32, 32, 4), 256, SMEM_TOTAL>>>(
        Qh, nullptr, Kh, nullptr, nullptr, S, nullptr, nullptr, nullptr, nullptr,
        4096, 768, 4096LL * 768, 4096LL * 768, 4096LL * 4096);

    softmax_pair<<<16384, 256>>>(S, Ph, Pl);

    // newV = P @ VT^T (2-pass, pair out)
    wm_gemm<2, false, false, 1><<<dim3(6, 32, 4), 256, SMEM_TOTAL>>>(
        Ph, Pl, VTs, nullptr, nullptr, nullptr, NVh, NVl, nullptr, nullptr,
        768, 4096, 4096LL * 4096, 768LL * 4096, 4096LL * 768);

    // H = relu(newV @ W1^T + b1) (2-pass, pair out)
    wm_gemm<2, true, true, 1><<<dim3(24, 128, 1), 256, SMEM_TOTAL>>>(
        NVh, NVl, W1s, nullptr, b1, nullptr, Hh, Hl, nullptr, nullptr,
        3072, 768, 0, 0, 0);

    // out = H @ W2^T + b2 (2-pass, fp32 out)
    wm_gemm<2, true, false, 0><<<dim3(6, 128, 1), 256, SMEM_TOTAL>>>(
        Hh, Hl, W2s, nullptr, b2, out, nullptr, nullptr, nullptr, nullptr,
        768, 3072, 0, 0, 0);
}